// round 1
// baseline (speedup 1.0000x reference)
#include <cuda_runtime.h>
#include <cuda_bf16.h>
#include <cstddef>

// ---------------------------------------------------------------------------
// TransNet: algebraically reduced implementation.
//   Layer solve:  v·(cI + dt^2 W^T W) = rhs_v + dt·rhs_u@W
//   u_out = -u = dt·v@W^T - rhs_u,  v_out = -v
//   (cI + dt^2 K)^{-1} = (1/c)(I - aK + a^2 K^2),  a = dt^2/c, K = W^T W
// All GEMMs are NT form: C[m,n] = sum_k A[m,k] * B[n,k]
// ---------------------------------------------------------------------------

#define BATCH   8192
#define UNITS   1024
#define INDIM   2048
#define OUTDIM  1000

static const float DT    = 0.1f;
static const float CCONST= 11.0f;            // 1 + dt/eps
static const float ACONST= 0.01f / 11.0f;    // dt^2 / c

// scratch (device globals: allocation-free per harness rules)
__device__ float g_b0[BATCH * UNITS];
__device__ float g_b1[BATCH * UNITS];
__device__ float g_b2[BATCH * UNITS];
__device__ float g_b3[BATCH * UNITS];
__device__ float g_s0[UNITS * UNITS];   // W^T
__device__ float g_s1[UNITS * UNITS];   // K = W^T W
__device__ float g_s2[UNITS * UNITS];   // T1 = I - aK
__device__ float g_s4[UNITS * UNITS];   // Minv

// ---------------------------------------------------------------------------
// NT GEMM: C = alpha * A@B^T (+ bias[n]) (+ add_scale*add[m,n]) (+ diag on m==n)
// A: [M,K] row-major, B: [N,K] row-major, C: [M,N] row-major.
// K must be a multiple of 16 and 4-float aligned rows (true for all calls).
// ---------------------------------------------------------------------------
__global__ __launch_bounds__(256) void gemm_nt(
    const float* __restrict__ A, const float* __restrict__ B,
    float* __restrict__ C, int M, int N, int K,
    float alpha,
    const float* __restrict__ bias, float diag_add,
    const float* __restrict__ addp, float add_scale)
{
    __shared__ float As[16][132];
    __shared__ float Bs[16][132];

    const int bm  = blockIdx.y * 128;
    const int bn  = blockIdx.x * 128;
    const int tid = threadIdx.x;
    const int tr  = tid >> 4;   // 0..15
    const int tc  = tid & 15;   // 0..15

    float acc[8][8];
#pragma unroll
    for (int i = 0; i < 8; ++i)
#pragma unroll
        for (int j = 0; j < 8; ++j) acc[i][j] = 0.0f;

    for (int kt = 0; kt < K; kt += 16) {
#pragma unroll
        for (int t = 0; t < 2; ++t) {
            int l   = tid + t * 256;
            int row = l >> 2;
            int kv  = (l & 3) << 2;
            float4 v = make_float4(0.f, 0.f, 0.f, 0.f);
            if (bm + row < M)
                v = *(const float4*)(A + (size_t)(bm + row) * K + kt + kv);
            As[kv + 0][row] = v.x; As[kv + 1][row] = v.y;
            As[kv + 2][row] = v.z; As[kv + 3][row] = v.w;
        }
#pragma unroll
        for (int t = 0; t < 2; ++t) {
            int l   = tid + t * 256;
            int row = l >> 2;
            int kv  = (l & 3) << 2;
            float4 v = make_float4(0.f, 0.f, 0.f, 0.f);
            if (bn + row < N)
                v = *(const float4*)(B + (size_t)(bn + row) * K + kt + kv);
            Bs[kv + 0][row] = v.x; Bs[kv + 1][row] = v.y;
            Bs[kv + 2][row] = v.z; Bs[kv + 3][row] = v.w;
        }
        __syncthreads();

#pragma unroll
        for (int k = 0; k < 16; ++k) {
            float ra[8], rb[8];
#pragma unroll
            for (int i = 0; i < 8; ++i) ra[i] = As[k][tr * 8 + i];
#pragma unroll
            for (int j = 0; j < 8; ++j) rb[j] = Bs[k][tc * 8 + j];
#pragma unroll
            for (int i = 0; i < 8; ++i)
#pragma unroll
                for (int j = 0; j < 8; ++j)
                    acc[i][j] = fmaf(ra[i], rb[j], acc[i][j]);
        }
        __syncthreads();
    }

#pragma unroll
    for (int i = 0; i < 8; ++i) {
        int m = bm + tr * 8 + i;
        if (m >= M) continue;
#pragma unroll
        for (int j = 0; j < 8; ++j) {
            int n = bn + tc * 8 + j;
            if (n >= N) continue;
            size_t idx = (size_t)m * N + n;
            float v = alpha * acc[i][j];
            if (bias) v += bias[n];
            if (addp) v += add_scale * addp[idx];
            if (m == n) v += diag_add;
            C[idx] = v;
        }
    }
}

// ---------------------------------------------------------------------------
__global__ void transpose_sq(float* __restrict__ dst, const float* __restrict__ src, int n)
{
    __shared__ float t[32][33];
    int x = blockIdx.x * 32 + threadIdx.x;
    int y = blockIdx.y * 32 + threadIdx.y;
    t[threadIdx.y][threadIdx.x] = src[(size_t)y * n + x];
    __syncthreads();
    int ox = blockIdx.y * 32 + threadIdx.x;
    int oy = blockIdx.x * 32 + threadIdx.y;
    dst[(size_t)oy * n + ox] = t[threadIdx.x][threadIdx.y];
}

__global__ void relu_copy(float* __restrict__ dst, const float* __restrict__ src, int n)
{
    int i = blockIdx.x * blockDim.x + threadIdx.x;
    if (i < n) dst[i] = fmaxf(src[i], 0.0f);
}

// dst = scale*src + diag*I   (square dim x dim)
__global__ void scale_diag(float* __restrict__ dst, const float* __restrict__ src,
                           float scale, float diag, int dim)
{
    int i = blockIdx.x * blockDim.x + threadIdx.x;
    if (i < dim * dim) {
        float v = scale * src[i];
        if ((i / dim) == (i % dim)) v += diag;
        dst[i] = v;
    }
}

// Ru = u + dt*b[col];  Rv = sv*vbuf + (dt/eps)*relu(u)
__global__ void build_rhs(const float* __restrict__ u, const float* __restrict__ vbuf,
                          const float* __restrict__ b, float sv,
                          float* __restrict__ Ru, float* __restrict__ Rv, int n)
{
    int i = blockIdx.x * blockDim.x + threadIdx.x;
    if (i < n) {
        int col = i & (UNITS - 1);
        float uv = u[i];
        Ru[i] = uv + 0.1f * b[col];
        Rv[i] = sv * vbuf[i] + 10.0f * fmaxf(uv, 0.0f);
    }
}

__global__ void softmax_rows(float* __restrict__ data, int cols)
{
    int row = blockIdx.x;
    float* d = data + (size_t)row * cols;
    __shared__ float sm[32];
    int tid = threadIdx.x, lane = tid & 31, warp = tid >> 5;
    int nwarp = blockDim.x >> 5;

    float m = -3.4e38f;
    for (int i = tid; i < cols; i += blockDim.x) m = fmaxf(m, d[i]);
#pragma unroll
    for (int o = 16; o; o >>= 1) m = fmaxf(m, __shfl_xor_sync(0xffffffffu, m, o));
    if (lane == 0) sm[warp] = m;
    __syncthreads();
    if (warp == 0) {
        float t = (lane < nwarp) ? sm[lane] : -3.4e38f;
#pragma unroll
        for (int o = 16; o; o >>= 1) t = fmaxf(t, __shfl_xor_sync(0xffffffffu, t, o));
        if (lane == 0) sm[0] = t;
    }
    __syncthreads();
    float mx = sm[0];
    __syncthreads();

    float s = 0.0f;
    for (int i = tid; i < cols; i += blockDim.x) {
        float e = expf(d[i] - mx);
        d[i] = e;
        s += e;
    }
#pragma unroll
    for (int o = 16; o; o >>= 1) s += __shfl_xor_sync(0xffffffffu, s, o);
    if (lane == 0) sm[warp] = s;
    __syncthreads();
    if (warp == 0) {
        float t = (lane < nwarp) ? sm[lane] : 0.0f;
#pragma unroll
        for (int o = 16; o; o >>= 1) t += __shfl_xor_sync(0xffffffffu, t, o);
        if (lane == 0) sm[0] = t;
    }
    __syncthreads();
    float inv = 1.0f / sm[0];
    for (int i = tid; i < cols; i += blockDim.x) d[i] *= inv;
}

// ---------------------------------------------------------------------------
extern "C" void kernel_launch(void* const* d_in, const int* in_sizes, int n_in,
                              void* d_out, int out_size)
{
    const float* x     = (const float*)d_in[0];
    const float* W_in  = (const float*)d_in[1];
    const float* b_in  = (const float*)d_in[2];
    const float* Ws[3] = {(const float*)d_in[3], (const float*)d_in[5], (const float*)d_in[7]};
    const float* bs[3] = {(const float*)d_in[4], (const float*)d_in[6], (const float*)d_in[8]};
    const float* W_out = (const float*)d_in[9];
    const float* b_out = (const float*)d_in[10];
    float* out = (float*)d_out;

    float *b0, *b1, *b2, *b3, *s0, *s1, *s2, *s4;
    cudaGetSymbolAddress((void**)&b0, g_b0);
    cudaGetSymbolAddress((void**)&b1, g_b1);
    cudaGetSymbolAddress((void**)&b2, g_b2);
    cudaGetSymbolAddress((void**)&b3, g_b3);
    cudaGetSymbolAddress((void**)&s0, g_s0);
    cudaGetSymbolAddress((void**)&s1, g_s1);
    cudaGetSymbolAddress((void**)&s2, g_s2);
    cudaGetSymbolAddress((void**)&s4, g_s4);

    const int NB = BATCH * UNITS;
    dim3 blk(256);
    dim3 gridBig(UNITS / 128, BATCH / 128);        // (8, 64)
    dim3 gridSmall(UNITS / 128, UNITS / 128);      // (8, 8)
    dim3 gridOut((OUTDIM + 127) / 128, BATCH / 128);
    dim3 tblk(32, 32), tgrid(UNITS / 32, UNITS / 32);
    int ewBlocks = (NB + 255) / 256;
    int sdBlocks = (UNITS * UNITS + 255) / 256;

    // z0 = x @ W_in^T + b_in   -> b0 (u_in)
    gemm_nt<<<gridBig, blk>>>(x, W_in, b0, BATCH, UNITS, INDIM,
                              1.0f, b_in, 0.0f, nullptr, 0.0f);
    // v_in = relu(z0)          -> b1
    relu_copy<<<ewBlocks, 256>>>(b1, b0, NB);

    float* pu  = b0;   // u buffer
    float* pv  = b1;   // v buffer (holds sv * v_in)
    float* pru = b2;   // Ru
    float* prv = b3;   // Rv

    for (int l = 0; l < 3; ++l) {
        const float* W = Ws[l];
        const float* bb = bs[l];
        float sv = (l == 0) ? 1.0f : -1.0f;

        // s0 = W^T
        transpose_sq<<<tgrid, tblk>>>(s0, W, UNITS);
        // s1 = K = W^T W     (NT with A=B=W^T since K[i,j] = sum_m W[m,i]W[m,j])
        gemm_nt<<<gridSmall, blk>>>(s0, s0, s1, UNITS, UNITS, UNITS,
                                    1.0f, nullptr, 0.0f, nullptr, 0.0f);
        // s2 = T1 = I - a*K
        scale_diag<<<sdBlocks, 256>>>(s2, s1, -ACONST, 1.0f, UNITS);
        // s4 = Minv = (1/c)(I - a*K@T1)   (T1 symmetric -> NT ok)
        gemm_nt<<<gridSmall, blk>>>(s1, s2, s4, UNITS, UNITS, UNITS,
                                    -ACONST / CCONST, nullptr, 1.0f / CCONST,
                                    nullptr, 0.0f);

        // Ru = u + dt*b ; Rv = sv*v + (dt/eps)*relu(u)
        build_rhs<<<ewBlocks, 256>>>(pu, pv, bb, sv, pru, prv, NB);
        // r = dt*Ru@W + Rv        -> pv   (B = W^T = s0)
        gemm_nt<<<gridBig, blk>>>(pru, s0, pv, BATCH, UNITS, UNITS,
                                  DT, nullptr, 0.0f, prv, 1.0f);
        // V = r @ Minv            -> prv  (Minv symmetric -> NT ok)
        gemm_nt<<<gridBig, blk>>>(pv, s4, prv, BATCH, UNITS, UNITS,
                                  1.0f, nullptr, 0.0f, nullptr, 0.0f);
        // u_out = dt*V@W^T - Ru   -> pu
        gemm_nt<<<gridBig, blk>>>(prv, W, pu, BATCH, UNITS, UNITS,
                                  DT, nullptr, 0.0f, pru, -1.0f);

        // next layer: v_in = -V (sign handled by sv), V lives in prv
        float* tmp = pv; pv = prv; prv = tmp;
    }

    // logits = u @ W_out^T + b_out -> out ; then softmax rows
    gemm_nt<<<gridOut, blk>>>(pu, W_out, out, BATCH, OUTDIM, UNITS,
                              1.0f, b_out, 0.0f, nullptr, 0.0f);
    softmax_rows<<<BATCH, 256>>>(out, OUTDIM);
}

// round 4
// speedup vs baseline: 2.9215x; 2.9215x over previous
#include <cuda_runtime.h>
#include <cuda_bf16.h>
#include <cstddef>
#include <cstdint>

// ---------------------------------------------------------------------------
// TransNet, mma.sync bf16 split-precision GEMM (HMMA path for compute_103).
//   Layer solve:  v·(cI + dt^2 W^T W) = rhs_v + dt·rhs_u@W
//   u_out = -u = dt·v@W^T - rhs_u,  v_out = -v
//   (cI + dt^2 K)^{-1} ≈ (1/c)(I - aK@(I-aK)),  a = dt^2/c
// All GEMMs NT: C[m,n] = sum_k A[m,k]*B[n,k], computed on tensor cores as
//   AhBh + AlBh + AhBl  (bf16 hi/lo split, fp32 accumulate)
// cp.async double-buffered smem pipeline, 256 threads, 8 warps (32x64 each).
// ---------------------------------------------------------------------------

#define BATCH   8192
#define UNITS   1024
#define INDIM   2048
#define OUTDIM  1000

static const float DT     = 0.1f;
static const float CCONST = 11.0f;           // 1 + dt/eps
static const float ACONST = 0.01f / 11.0f;   // dt^2 / c

// ------------------------------- scratch (16B+ aligned!) -------------------
__device__ __align__(256) float g_b0[BATCH * UNITS];
__device__ __align__(256) float g_b1[BATCH * UNITS];
__device__ __align__(256) float g_b2[BATCH * UNITS];
__device__ __align__(256) float g_b3[BATCH * UNITS];
__device__ __align__(256) float g_s1[UNITS * UNITS];   // K fp32
__device__ __align__(256) float g_s4[UNITS * UNITS];   // Minv fp32 (dump)

__device__ __align__(256) unsigned short g_xh[BATCH * INDIM];
__device__ __align__(256) unsigned short g_xl[BATCH * INDIM];
__device__ __align__(256) unsigned short g_winh[UNITS * INDIM];
__device__ __align__(256) unsigned short g_winl[UNITS * INDIM];
__device__ __align__(256) unsigned short g_hah[BATCH * UNITS];
__device__ __align__(256) unsigned short g_hal[BATCH * UNITS];
__device__ __align__(256) unsigned short g_hbh[BATCH * UNITS];
__device__ __align__(256) unsigned short g_hbl[BATCH * UNITS];
__device__ __align__(256) unsigned short g_wh[UNITS * UNITS];
__device__ __align__(256) unsigned short g_wl[UNITS * UNITS];
__device__ __align__(256) unsigned short g_s0h[UNITS * UNITS];
__device__ __align__(256) unsigned short g_s0l[UNITS * UNITS];
__device__ __align__(256) unsigned short g_kh[UNITS * UNITS];
__device__ __align__(256) unsigned short g_kl[UNITS * UNITS];
__device__ __align__(256) unsigned short g_t1h[UNITS * UNITS];
__device__ __align__(256) unsigned short g_t1l[UNITS * UNITS];
__device__ __align__(256) unsigned short g_mih[UNITS * UNITS];
__device__ __align__(256) unsigned short g_mil[UNITS * UNITS];
__device__ __align__(256) unsigned short g_woh[OUTDIM * UNITS];
__device__ __align__(256) unsigned short g_wol[OUTDIM * UNITS];

// ------------------------------ helpers ------------------------------------
#define SWZ(o) ((o) ^ (((o) >> 3) & 0x70u))

__device__ __forceinline__ uint32_t smem_u32(const void* p) {
    uint32_t a;
    asm("{ .reg .u64 t; cvta.to.shared.u64 t, %1; cvt.u32.u64 %0, t; }"
        : "=r"(a) : "l"(p));
    return a;
}

// cp.async 16B global->shared; src_sz=0 zero-fills (OOB rows)
__device__ __forceinline__ void cp16(uint32_t dst, const void* src, bool inb) {
    int sz = inb ? 16 : 0;
    asm volatile(
        "{\n\t.reg .u64 g;\n\tcvta.to.global.u64 g, %1;\n\t"
        "cp.async.cg.shared.global [%0], [g], 16, %2;\n\t}"
        :: "r"(dst), "l"(src), "r"(sz) : "memory");
}
__device__ __forceinline__ void cp_commit() {
    asm volatile("cp.async.commit_group;" ::: "memory");
}
__device__ __forceinline__ void cp_wait0() {
    asm volatile("cp.async.wait_group 0;" ::: "memory");
}
__device__ __forceinline__ void cp_wait1() {
    asm volatile("cp.async.wait_group 1;" ::: "memory");
}

// mma.sync m16n8k16 row.col f32 <- bf16 x bf16 + f32
__device__ __forceinline__ void mma16816(float* d, const uint32_t* a, const uint32_t* b) {
    asm volatile(
        "mma.sync.aligned.m16n8k16.row.col.f32.bf16.bf16.f32 "
        "{%0,%1,%2,%3}, {%4,%5,%6,%7}, {%8,%9}, {%0,%1,%2,%3};"
        : "+f"(d[0]), "+f"(d[1]), "+f"(d[2]), "+f"(d[3])
        : "r"(a[0]), "r"(a[1]), "r"(a[2]), "r"(a[3]), "r"(b[0]), "r"(b[1]));
}

// --------------------------- GEMM kernel -----------------------------------
// C[m,n] = alpha * sum_k A[m,k]B[n,k] (+bias[n]) (+add_scale*addp[m,n]) (+diag)
// A,B bf16 hi/lo pairs (K-major). M % 128 == 0, K % 64 == 0, N % 2 == 0.
#define BM 128
#define BN 128
#define BK 64
#define TILE_B   (128 * 128)              // bytes per operand tile
#define STAGE_B  (4 * TILE_B)             // Ah, Al, Bh, Bl
#define SMEM_GEMM (1024 + 2 * STAGE_B)    // 132096

__global__ __launch_bounds__(256) void gemm_tc(
    const unsigned short* __restrict__ Ah, const unsigned short* __restrict__ Al,
    const unsigned short* __restrict__ Bh, const unsigned short* __restrict__ Bl,
    float* __restrict__ C,
    unsigned short* __restrict__ Ch, unsigned short* __restrict__ Cl,
    int M, int N, int K, float alpha,
    const float* __restrict__ bias, float diag_add,
    const float* __restrict__ addp, float add_scale)
{
    extern __shared__ char smem[];
    const uint32_t sbase = smem_u32(smem) + 1024;
    const int tid  = threadIdx.x;
    const int wid  = tid >> 5;
    const int lane = tid & 31;
    const int bm = blockIdx.y * BM;
    const int bn = blockIdx.x * BN;
    const int nc = K / BK;

    const unsigned short* srcs[4] = {Ah, Al, Bh, Bl};
    const int r0s[4] = {bm, bm, bn, bn};
    const int nrs[4] = {M, M, N, N};

    // per-thread fixed load slot
    const int lrow = tid >> 3;            // 0..31 (row group of 32 per iter)
    const int lsc  = tid & 7;             // 16B column within 128B row
    const uint32_t lswz_base = (uint32_t)lsc * 16u;

    auto issue_stage = [&](int c) {
        const int buf = c & 1;
        const int k0 = c * BK;
        const uint32_t sdst = sbase + buf * STAGE_B;
#pragma unroll
        for (int t = 0; t < 4; ++t) {
#pragma unroll
            for (int i = 0; i < 4; ++i) {
                int row = lrow + i * 32;
                uint32_t off = (uint32_t)row * 128u + lswz_base;
                cp16(sdst + t * TILE_B + SWZ(off),
                     srcs[t] + (size_t)(r0s[t] + row) * K + k0 + lsc * 8,
                     r0s[t] + row < nrs[t]);
            }
        }
        cp_commit();
    };

    // warp tiling: warp (wm, wn) owns rows [wm*32,+32) x cols [wn*64,+64)
    const int wm = wid & 3;
    const int wn = wid >> 2;
    const int r  = lane >> 2;          // 0..7
    const int c2 = (lane & 3) * 2;     // 0,2,4,6

    float acc[2][8][4];
#pragma unroll
    for (int a = 0; a < 2; ++a)
#pragma unroll
        for (int b = 0; b < 8; ++b)
#pragma unroll
            for (int q = 0; q < 4; ++q) acc[a][b][q] = 0.0f;

    issue_stage(0);
    for (int c = 0; c < nc; ++c) {
        if (c + 1 < nc) { issue_stage(c + 1); cp_wait1(); }
        else           { cp_wait0(); }
        __syncthreads();

        const char* st  = smem + 1024 + (c & 1) * STAGE_B;
        const char* tAh = st;
        const char* tAl = st + TILE_B;
        const char* tBh = st + 2 * TILE_B;
        const char* tBl = st + 3 * TILE_B;

#pragma unroll
        for (int ks = 0; ks < 4; ++ks) {
            const int k0 = ks * 16;
            uint32_t ah[2][4], al[2][4];
#pragma unroll
            for (int mt = 0; mt < 2; ++mt) {
                uint32_t base = (uint32_t)(wm * 32 + mt * 16 + r) * 128u
                              + (uint32_t)(k0 + c2) * 2u;
                uint32_t o0 = base, o1 = base + 8 * 128, o2 = base + 16, o3 = o1 + 16;
                ah[mt][0] = *(const uint32_t*)(tAh + SWZ(o0));
                ah[mt][1] = *(const uint32_t*)(tAh + SWZ(o1));
                ah[mt][2] = *(const uint32_t*)(tAh + SWZ(o2));
                ah[mt][3] = *(const uint32_t*)(tAh + SWZ(o3));
                al[mt][0] = *(const uint32_t*)(tAl + SWZ(o0));
                al[mt][1] = *(const uint32_t*)(tAl + SWZ(o1));
                al[mt][2] = *(const uint32_t*)(tAl + SWZ(o2));
                al[mt][3] = *(const uint32_t*)(tAl + SWZ(o3));
            }
            uint32_t bhf[8][2], blf[8][2];
#pragma unroll
            for (int nt = 0; nt < 8; ++nt) {
                uint32_t base = (uint32_t)(wn * 64 + nt * 8 + r) * 128u
                              + (uint32_t)(k0 + c2) * 2u;
                bhf[nt][0] = *(const uint32_t*)(tBh + SWZ(base));
                bhf[nt][1] = *(const uint32_t*)(tBh + SWZ(base + 16));
                blf[nt][0] = *(const uint32_t*)(tBl + SWZ(base));
                blf[nt][1] = *(const uint32_t*)(tBl + SWZ(base + 16));
            }
#pragma unroll
            for (int nt = 0; nt < 8; ++nt) {
                mma16816(acc[0][nt], ah[0], bhf[nt]);
                mma16816(acc[1][nt], ah[1], bhf[nt]);
            }
#pragma unroll
            for (int nt = 0; nt < 8; ++nt) {
                mma16816(acc[0][nt], al[0], bhf[nt]);
                mma16816(acc[1][nt], al[1], bhf[nt]);
            }
#pragma unroll
            for (int nt = 0; nt < 8; ++nt) {
                mma16816(acc[0][nt], ah[0], blf[nt]);
                mma16816(acc[1][nt], ah[1], blf[nt]);
            }
        }
        __syncthreads();
    }

    // epilogue
#pragma unroll
    for (int mt = 0; mt < 2; ++mt) {
#pragma unroll
        for (int nt = 0; nt < 8; ++nt) {
            const int col = bn + wn * 64 + nt * 8 + c2;
            if (col >= N) continue;
            float bx = 0.f, by = 0.f;
            if (bias) { bx = bias[col]; by = bias[col + 1]; }
#pragma unroll
            for (int h = 0; h < 2; ++h) {
                const int m = bm + wm * 32 + mt * 16 + r + h * 8;
                float d0 = alpha * acc[mt][nt][2 * h + 0] + bx;
                float d1 = alpha * acc[mt][nt][2 * h + 1] + by;
                size_t idx = (size_t)m * N + col;
                if (addp) {
                    d0 += add_scale * addp[idx];
                    d1 += add_scale * addp[idx + 1];
                }
                if (diag_add != 0.0f) {
                    if (m == col)     d0 += diag_add;
                    if (m == col + 1) d1 += diag_add;
                }
                *(float2*)(C + idx) = make_float2(d0, d1);
                if (Ch) {
                    __nv_bfloat16 h0 = __float2bfloat16(d0);
                    __nv_bfloat16 h1 = __float2bfloat16(d1);
                    ushort2 hs = make_ushort2(__bfloat16_as_ushort(h0),
                                              __bfloat16_as_ushort(h1));
                    ushort2 ls = make_ushort2(
                        __bfloat16_as_ushort(__float2bfloat16(d0 - __bfloat162float(h0))),
                        __bfloat16_as_ushort(__float2bfloat16(d1 - __bfloat162float(h1))));
                    *(ushort2*)(Ch + idx) = hs;
                    *(ushort2*)(Cl + idx) = ls;
                }
            }
        }
    }
}

// ----------------------------- elementwise ---------------------------------
__device__ __forceinline__ void split1(float x, unsigned short& h, unsigned short& l) {
    __nv_bfloat16 hb = __float2bfloat16(x);
    h = __bfloat16_as_ushort(hb);
    l = __bfloat16_as_ushort(__float2bfloat16(x - __bfloat162float(hb)));
}

__global__ void split_hl(const float* __restrict__ src,
                         unsigned short* __restrict__ h,
                         unsigned short* __restrict__ l, int n)
{
    int i = blockIdx.x * blockDim.x + threadIdx.x;
    if (i * 4 < n) {
        float4 v = *(const float4*)(src + i * 4);
        ushort4 hs, ls;
        split1(v.x, hs.x, ls.x); split1(v.y, hs.y, ls.y);
        split1(v.z, hs.z, ls.z); split1(v.w, hs.w, ls.w);
        *(ushort4*)(h + i * 4) = hs;
        *(ushort4*)(l + i * 4) = ls;
    }
}

__global__ void transpose_split(unsigned short* __restrict__ dh,
                                unsigned short* __restrict__ dl,
                                const float* __restrict__ src, int n)
{
    __shared__ float t[32][33];
    int x = blockIdx.x * 32 + threadIdx.x;
    int y = blockIdx.y * 32 + threadIdx.y;
    t[threadIdx.y][threadIdx.x] = src[(size_t)y * n + x];
    __syncthreads();
    int ox = blockIdx.y * 32 + threadIdx.x;
    int oy = blockIdx.x * 32 + threadIdx.y;
    unsigned short h, l;
    split1(t[threadIdx.x][threadIdx.y], h, l);
    dh[(size_t)oy * n + ox] = h;
    dl[(size_t)oy * n + ox] = l;
}

__global__ void relu_copy(float* __restrict__ dst, const float* __restrict__ src, int n)
{
    int i = blockIdx.x * blockDim.x + threadIdx.x;
    if (i < n) dst[i] = fmaxf(src[i], 0.0f);
}

__global__ void scale_diag_split(unsigned short* __restrict__ dh,
                                 unsigned short* __restrict__ dl,
                                 const float* __restrict__ src,
                                 float scale, float diag, int dim)
{
    int i = blockIdx.x * blockDim.x + threadIdx.x;
    if (i < dim * dim) {
        float v = scale * src[i];
        if ((i / dim) == (i % dim)) v += diag;
        unsigned short h, l;
        split1(v, h, l);
        dh[i] = h; dl[i] = l;
    }
}

__global__ void build_rhs_split(const float* __restrict__ u, const float* __restrict__ vbuf,
                                const float* __restrict__ b, float sv,
                                float* __restrict__ Ru,
                                unsigned short* __restrict__ Ruh,
                                unsigned short* __restrict__ Rul,
                                float* __restrict__ Rv, int n)
{
    int i = blockIdx.x * blockDim.x + threadIdx.x;
    if (i < n) {
        int col = i & (UNITS - 1);
        float uv = u[i];
        float ru = uv + 0.1f * b[col];
        Ru[i] = ru;
        unsigned short h, l;
        split1(ru, h, l);
        Ruh[i] = h; Rul[i] = l;
        Rv[i] = sv * vbuf[i] + 10.0f * fmaxf(uv, 0.0f);
    }
}

__global__ void softmax_rows(float* __restrict__ data, int cols)
{
    int row = blockIdx.x;
    float* d = data + (size_t)row * cols;
    __shared__ float sm[32];
    int tid = threadIdx.x, lane = tid & 31, warp = tid >> 5;
    int nwarp = blockDim.x >> 5;

    float m = -3.4e38f;
    for (int i = tid; i < cols; i += blockDim.x) m = fmaxf(m, d[i]);
#pragma unroll
    for (int o = 16; o; o >>= 1) m = fmaxf(m, __shfl_xor_sync(0xffffffffu, m, o));
    if (lane == 0) sm[warp] = m;
    __syncthreads();
    if (warp == 0) {
        float t = (lane < nwarp) ? sm[lane] : -3.4e38f;
#pragma unroll
        for (int o = 16; o; o >>= 1) t = fmaxf(t, __shfl_xor_sync(0xffffffffu, t, o));
        if (lane == 0) sm[0] = t;
    }
    __syncthreads();
    float mx = sm[0];
    __syncthreads();

    float s = 0.0f;
    for (int i = tid; i < cols; i += blockDim.x) {
        float e = expf(d[i] - mx);
        d[i] = e;
        s += e;
    }
#pragma unroll
    for (int o = 16; o; o >>= 1) s += __shfl_xor_sync(0xffffffffu, s, o);
    if (lane == 0) sm[warp] = s;
    __syncthreads();
    if (warp == 0) {
        float t = (lane < nwarp) ? sm[lane] : 0.0f;
#pragma unroll
        for (int o = 16; o; o >>= 1) t += __shfl_xor_sync(0xffffffffu, t, o);
        if (lane == 0) sm[0] = t;
    }
    __syncthreads();
    float inv = 1.0f / sm[0];
    for (int i = tid; i < cols; i += blockDim.x) d[i] *= inv;
}

// ---------------------------------------------------------------------------
extern "C" void kernel_launch(void* const* d_in, const int* in_sizes, int n_in,
                              void* d_out, int out_size)
{
    const float* x     = (const float*)d_in[0];
    const float* W_in  = (const float*)d_in[1];
    const float* b_in  = (const float*)d_in[2];
    const float* Ws[3] = {(const float*)d_in[3], (const float*)d_in[5], (const float*)d_in[7]};
    const float* bs[3] = {(const float*)d_in[4], (const float*)d_in[6], (const float*)d_in[8]};
    const float* W_out = (const float*)d_in[9];
    const float* b_out = (const float*)d_in[10];
    float* out = (float*)d_out;

    cudaFuncSetAttribute(gemm_tc, cudaFuncAttributeMaxDynamicSharedMemorySize, SMEM_GEMM);

    float *b0, *b1, *b2, *b3, *s1, *s4;
    cudaGetSymbolAddress((void**)&b0, g_b0);
    cudaGetSymbolAddress((void**)&b1, g_b1);
    cudaGetSymbolAddress((void**)&b2, g_b2);
    cudaGetSymbolAddress((void**)&b3, g_b3);
    cudaGetSymbolAddress((void**)&s1, g_s1);
    cudaGetSymbolAddress((void**)&s4, g_s4);
    unsigned short *xh, *xl, *winh, *winl, *hah, *hal, *hbh, *hbl;
    unsigned short *wh, *wl, *s0h, *s0l, *kh, *kl, *t1h, *t1l, *mih, *mil, *woh, *wol;
    cudaGetSymbolAddress((void**)&xh, g_xh);   cudaGetSymbolAddress((void**)&xl, g_xl);
    cudaGetSymbolAddress((void**)&winh, g_winh); cudaGetSymbolAddress((void**)&winl, g_winl);
    cudaGetSymbolAddress((void**)&hah, g_hah); cudaGetSymbolAddress((void**)&hal, g_hal);
    cudaGetSymbolAddress((void**)&hbh, g_hbh); cudaGetSymbolAddress((void**)&hbl, g_hbl);
    cudaGetSymbolAddress((void**)&wh, g_wh);   cudaGetSymbolAddress((void**)&wl, g_wl);
    cudaGetSymbolAddress((void**)&s0h, g_s0h); cudaGetSymbolAddress((void**)&s0l, g_s0l);
    cudaGetSymbolAddress((void**)&kh, g_kh);   cudaGetSymbolAddress((void**)&kl, g_kl);
    cudaGetSymbolAddress((void**)&t1h, g_t1h); cudaGetSymbolAddress((void**)&t1l, g_t1l);
    cudaGetSymbolAddress((void**)&mih, g_mih); cudaGetSymbolAddress((void**)&mil, g_mil);
    cudaGetSymbolAddress((void**)&woh, g_woh); cudaGetSymbolAddress((void**)&wol, g_wol);

    const int NB = BATCH * UNITS;
    dim3 gBig(UNITS / BN, BATCH / BM);                 // (8, 64)
    dim3 gSmall(UNITS / BN, UNITS / BM);               // (8, 8)
    dim3 gOut((OUTDIM + BN - 1) / BN, BATCH / BM);     // (8, 64)
    dim3 tblk(32, 32), tgrid(UNITS / 32, UNITS / 32);
    int ewBlocks = (NB + 255) / 256;
    int sdBlocks = (UNITS * UNITS + 255) / 256;

    // one-time splits of inputs
    split_hl<<<(BATCH * INDIM / 4 + 255) / 256, 256>>>(x, xh, xl, BATCH * INDIM);
    split_hl<<<(UNITS * INDIM / 4 + 255) / 256, 256>>>(W_in, winh, winl, UNITS * INDIM);
    split_hl<<<(OUTDIM * UNITS / 4 + 255) / 256, 256>>>(W_out, woh, wol, OUTDIM * UNITS);

    // z0 = x @ W_in^T + b_in -> b0 (u_in)
    gemm_tc<<<gBig, 256, SMEM_GEMM>>>(xh, xl, winh, winl, b0, nullptr, nullptr,
                                      BATCH, UNITS, INDIM, 1.0f, b_in, 0.0f, nullptr, 0.0f);
    relu_copy<<<ewBlocks, 256>>>(b1, b0, NB);

    float* pu  = b0;
    float* pv  = b1;
    float* pru = b2;
    float* prv = b3;

    for (int l = 0; l < 3; ++l) {
        const float* W  = Ws[l];
        const float* bb = bs[l];
        float sv = (l == 0) ? 1.0f : -1.0f;

        transpose_split<<<tgrid, tblk>>>(s0h, s0l, W, UNITS);              // W^T
        split_hl<<<(UNITS * UNITS / 4 + 255) / 256, 256>>>(W, wh, wl, UNITS * UNITS);
        // K = W^T W
        gemm_tc<<<gSmall, 256, SMEM_GEMM>>>(s0h, s0l, s0h, s0l, s1, kh, kl,
                                            UNITS, UNITS, UNITS, 1.0f, nullptr, 0.0f,
                                            nullptr, 0.0f);
        // T1 = I - aK
        scale_diag_split<<<sdBlocks, 256>>>(t1h, t1l, s1, -ACONST, 1.0f, UNITS);
        // Minv = -(a/c) K@T1 + (1/c) I
        gemm_tc<<<gSmall, 256, SMEM_GEMM>>>(kh, kl, t1h, t1l, s4, mih, mil,
                                            UNITS, UNITS, UNITS, -ACONST / CCONST,
                                            nullptr, 1.0f / CCONST, nullptr, 0.0f);

        build_rhs_split<<<ewBlocks, 256>>>(pu, pv, bb, sv, pru, hah, hal, prv, NB);
        // r = dt*Ru@W + Rv        (B = W^T)
        gemm_tc<<<gBig, 256, SMEM_GEMM>>>(hah, hal, s0h, s0l, pv, hbh, hbl,
                                          BATCH, UNITS, UNITS, DT, nullptr, 0.0f,
                                          prv, 1.0f);
        // V = r @ Minv
        gemm_tc<<<gBig, 256, SMEM_GEMM>>>(hbh, hbl, mih, mil, prv, hah, hal,
                                          BATCH, UNITS, UNITS, 1.0f, nullptr, 0.0f,
                                          nullptr, 0.0f);
        // u_out = dt*V@W^T - Ru
        gemm_tc<<<gBig, 256, SMEM_GEMM>>>(hah, hal, wh, wl, pu, hbh, hbl,
                                          BATCH, UNITS, UNITS, DT, nullptr, 0.0f,
                                          pru, -1.0f);

        float* tmp = pv; pv = prv; prv = tmp;
    }

    // logits = u @ W_out^T + b_out -> out ; softmax
    gemm_tc<<<gOut, 256, SMEM_GEMM>>>(hbh, hbl, woh, wol, out, nullptr, nullptr,
                                      BATCH, OUTDIM, UNITS, 1.0f, b_out, 0.0f,
                                      nullptr, 0.0f);
    softmax_rows<<<BATCH, 256>>>(out, OUTDIM);
}

// round 5
// speedup vs baseline: 3.2172x; 1.1013x over previous
#include <cuda_runtime.h>
#include <cuda_bf16.h>
#include <cstddef>
#include <cstdint>

// ---------------------------------------------------------------------------
// TransNet, mma.sync bf16 split-precision GEMM, ldmatrix fragment loads.
//   Layer solve:  v·(cI + dt^2 W^T W) = rhs_v + dt·rhs_u@W
//   u_out = -u = dt·v@W^T - rhs_u,  v_out = -v
//   (cI + dt^2 K)^{-1} ≈ (1/c)(I - aK)   [first-order Neumann, err ~1.5e-6]
// All GEMMs NT: C[m,n] = sum_k A[m,k]*B[n,k], computed on tensor cores as
//   AhBh + AlBh + AhBl  (bf16 hi/lo split, fp32 accumulate)
// ---------------------------------------------------------------------------

#define BATCH   8192
#define UNITS   1024
#define INDIM   2048
#define OUTDIM  1000

static const float DT     = 0.1f;
static const float CCONST = 11.0f;           // 1 + dt/eps
static const float ACONST = 0.01f / 11.0f;   // dt^2 / c

// ------------------------------- scratch (16B+ aligned) --------------------
__device__ __align__(256) float g_b0[BATCH * UNITS];
__device__ __align__(256) float g_b1[BATCH * UNITS];
__device__ __align__(256) float g_b2[BATCH * UNITS];
__device__ __align__(256) float g_b3[BATCH * UNITS];
__device__ __align__(256) float g_s1[UNITS * UNITS];   // K fp32

__device__ __align__(256) unsigned short g_xh[BATCH * INDIM];
__device__ __align__(256) unsigned short g_xl[BATCH * INDIM];
__device__ __align__(256) unsigned short g_winh[UNITS * INDIM];
__device__ __align__(256) unsigned short g_winl[UNITS * INDIM];
__device__ __align__(256) unsigned short g_hah[BATCH * UNITS];
__device__ __align__(256) unsigned short g_hal[BATCH * UNITS];
__device__ __align__(256) unsigned short g_hbh[BATCH * UNITS];
__device__ __align__(256) unsigned short g_hbl[BATCH * UNITS];
__device__ __align__(256) unsigned short g_wh[UNITS * UNITS];
__device__ __align__(256) unsigned short g_wl[UNITS * UNITS];
__device__ __align__(256) unsigned short g_s0h[UNITS * UNITS];
__device__ __align__(256) unsigned short g_s0l[UNITS * UNITS];
__device__ __align__(256) unsigned short g_mih[UNITS * UNITS];
__device__ __align__(256) unsigned short g_mil[UNITS * UNITS];
__device__ __align__(256) unsigned short g_woh[OUTDIM * UNITS];
__device__ __align__(256) unsigned short g_wol[OUTDIM * UNITS];

// ------------------------------ helpers ------------------------------------
#define SWZ(o) ((o) ^ (((o) >> 3) & 0x70u))

__device__ __forceinline__ uint32_t smem_u32(const void* p) {
    uint32_t a;
    asm("{ .reg .u64 t; cvta.to.shared.u64 t, %1; cvt.u32.u64 %0, t; }"
        : "=r"(a) : "l"(p));
    return a;
}

// cp.async 16B global->shared; src_sz=0 zero-fills (OOB rows)
__device__ __forceinline__ void cp16(uint32_t dst, const void* src, bool inb) {
    int sz = inb ? 16 : 0;
    asm volatile(
        "{\n\t.reg .u64 g;\n\tcvta.to.global.u64 g, %1;\n\t"
        "cp.async.cg.shared.global [%0], [g], 16, %2;\n\t}"
        :: "r"(dst), "l"(src), "r"(sz) : "memory");
}
__device__ __forceinline__ void cp_commit() {
    asm volatile("cp.async.commit_group;" ::: "memory");
}
__device__ __forceinline__ void cp_wait0() {
    asm volatile("cp.async.wait_group 0;" ::: "memory");
}
__device__ __forceinline__ void cp_wait1() {
    asm volatile("cp.async.wait_group 1;" ::: "memory");
}

// mma.sync m16n8k16 row.col f32 <- bf16 x bf16 + f32
__device__ __forceinline__ void mma16816(float* d, const uint32_t* a, const uint32_t* b) {
    asm volatile(
        "mma.sync.aligned.m16n8k16.row.col.f32.bf16.bf16.f32 "
        "{%0,%1,%2,%3}, {%4,%5,%6,%7}, {%8,%9}, {%0,%1,%2,%3};"
        : "+f"(d[0]), "+f"(d[1]), "+f"(d[2]), "+f"(d[3])
        : "r"(a[0]), "r"(a[1]), "r"(a[2]), "r"(a[3]), "r"(b[0]), "r"(b[1]));
}

// ldmatrix x4: four 8x8 b16 matrices, per-lane row addresses
__device__ __forceinline__ void ldsm4(uint32_t* r, uint32_t addr) {
    asm volatile("ldmatrix.sync.aligned.m8n8.x4.shared.b16 {%0,%1,%2,%3}, [%4];"
        : "=r"(r[0]), "=r"(r[1]), "=r"(r[2]), "=r"(r[3]) : "r"(addr));
}

// --------------------------- GEMM kernel -----------------------------------
// C[m,n] = alpha * sum_k A[m,k]B[n,k] (+bias[n]) (+add_scale*addp[m,n]) (+diag)
// Optional outputs: C fp32, Crelu = relu(C) fp32, (Ch, Cl) bf16 hi/lo split.
// A,B bf16 hi/lo pairs (K-major). M % 128 == 0, K % 64 == 0, N % 2 == 0.
#define BM 128
#define BN 128
#define BK 64
#define TILE_B   (128 * 128)              // bytes per operand tile
#define STAGE_B  (4 * TILE_B)             // Ah, Al, Bh, Bl
#define SMEM_GEMM (1024 + 2 * STAGE_B)    // 132096

__global__ __launch_bounds__(256) void gemm_tc(
    const unsigned short* __restrict__ Ah, const unsigned short* __restrict__ Al,
    const unsigned short* __restrict__ Bh, const unsigned short* __restrict__ Bl,
    float* __restrict__ C, float* __restrict__ Crelu,
    unsigned short* __restrict__ Ch, unsigned short* __restrict__ Cl,
    int M, int N, int K, float alpha,
    const float* __restrict__ bias, float diag_add,
    const float* __restrict__ addp, float add_scale)
{
    extern __shared__ char smem[];
    const uint32_t sbase = smem_u32(smem) + 1024;
    const int tid  = threadIdx.x;
    const int wid  = tid >> 5;
    const int lane = tid & 31;
    const int bm = blockIdx.y * BM;
    const int bn = blockIdx.x * BN;
    const int nc = K / BK;

    const unsigned short* srcs[4] = {Ah, Al, Bh, Bl};
    const int r0s[4] = {bm, bm, bn, bn};
    const int nrs[4] = {M, M, N, N};

    // per-thread fixed cp.async slot
    const int lrow = tid >> 3;            // 0..31
    const int lsc  = tid & 7;             // 16B column
    const uint32_t lswz_base = (uint32_t)lsc * 16u;

    auto issue_stage = [&](int c) {
        const int buf = c & 1;
        const int k0 = c * BK;
        const uint32_t sdst = sbase + buf * STAGE_B;
#pragma unroll
        for (int t = 0; t < 4; ++t) {
#pragma unroll
            for (int i = 0; i < 4; ++i) {
                int row = lrow + i * 32;
                uint32_t off = (uint32_t)row * 128u + lswz_base;
                cp16(sdst + t * TILE_B + SWZ(off),
                     srcs[t] + (size_t)(r0s[t] + row) * K + k0 + lsc * 8,
                     r0s[t] + row < nrs[t]);
            }
        }
        cp_commit();
    };

    // warp tiling: warp (wm, wn) owns rows [wm*32,+32) x cols [wn*64,+64)
    const int wm = wid & 3;
    const int wn = wid >> 2;
    const int r  = lane >> 2;
    const int c2 = (lane & 3) * 2;

    // ldmatrix per-lane addressing
    const int q   = lane >> 3;            // 0..3
    const int rin = lane & 7;             // row within 8
    const uint32_t a_row = (uint32_t)(wm * 32 + (q & 1) * 8 + rin) * 128u;
    const int a_sel = q >> 1;             // 16B chunk select
    const uint32_t b_row = (uint32_t)(wn * 64 + (q >> 1) * 8 + rin) * 128u;
    const int b_sel = q & 1;

    float acc[2][8][4];
#pragma unroll
    for (int a = 0; a < 2; ++a)
#pragma unroll
        for (int b = 0; b < 8; ++b)
#pragma unroll
            for (int k = 0; k < 4; ++k) acc[a][b][k] = 0.0f;

    issue_stage(0);
    for (int c = 0; c < nc; ++c) {
        if (c + 1 < nc) { issue_stage(c + 1); cp_wait1(); }
        else           { cp_wait0(); }
        __syncthreads();

        const uint32_t tAh = sbase + (c & 1) * STAGE_B;
        const uint32_t tAl = tAh + TILE_B;
        const uint32_t tBh = tAh + 2 * TILE_B;
        const uint32_t tBl = tAh + 3 * TILE_B;

#pragma unroll
        for (int ks = 0; ks < 4; ++ks) {
            // swizzled 16B-chunk offset within the 128B row
            const uint32_t aoff = ((uint32_t)((ks * 2 + a_sel) ^ rin)) << 4;
            const uint32_t boff = ((uint32_t)((ks * 2 + b_sel) ^ rin)) << 4;

            uint32_t ah[2][4], al[2][4];
            ldsm4(ah[0], tAh + a_row + aoff);
            ldsm4(ah[1], tAh + a_row + 2048u + aoff);   // +16 rows
            ldsm4(al[0], tAl + a_row + aoff);
            ldsm4(al[1], tAl + a_row + 2048u + aoff);

            uint32_t bh[8][2], bl[8][2];
#pragma unroll
            for (int p = 0; p < 4; ++p) {
                uint32_t r4[4];
                ldsm4(r4, tBh + b_row + (uint32_t)p * 2048u + boff);
                bh[2 * p][0] = r4[0]; bh[2 * p][1] = r4[1];
                bh[2 * p + 1][0] = r4[2]; bh[2 * p + 1][1] = r4[3];
                ldsm4(r4, tBl + b_row + (uint32_t)p * 2048u + boff);
                bl[2 * p][0] = r4[0]; bl[2 * p][1] = r4[1];
                bl[2 * p + 1][0] = r4[2]; bl[2 * p + 1][1] = r4[3];
            }

#pragma unroll
            for (int nt = 0; nt < 8; ++nt) {
                mma16816(acc[0][nt], ah[0], bh[nt]);
                mma16816(acc[1][nt], ah[1], bh[nt]);
            }
#pragma unroll
            for (int nt = 0; nt < 8; ++nt) {
                mma16816(acc[0][nt], al[0], bh[nt]);
                mma16816(acc[1][nt], al[1], bh[nt]);
            }
#pragma unroll
            for (int nt = 0; nt < 8; ++nt) {
                mma16816(acc[0][nt], ah[0], bl[nt]);
                mma16816(acc[1][nt], ah[1], bl[nt]);
            }
        }
        __syncthreads();
    }

    // epilogue
#pragma unroll
    for (int mt = 0; mt < 2; ++mt) {
#pragma unroll
        for (int nt = 0; nt < 8; ++nt) {
            const int col = bn + wn * 64 + nt * 8 + c2;
            if (col >= N) continue;
            float bx = 0.f, by = 0.f;
            if (bias) { bx = bias[col]; by = bias[col + 1]; }
#pragma unroll
            for (int h = 0; h < 2; ++h) {
                const int m = bm + wm * 32 + mt * 16 + r + h * 8;
                float d0 = alpha * acc[mt][nt][2 * h + 0] + bx;
                float d1 = alpha * acc[mt][nt][2 * h + 1] + by;
                size_t idx = (size_t)m * N + col;
                if (addp) {
                    d0 += add_scale * addp[idx];
                    d1 += add_scale * addp[idx + 1];
                }
                if (diag_add != 0.0f) {
                    if (m == col)     d0 += diag_add;
                    if (m == col + 1) d1 += diag_add;
                }
                if (C)     *(float2*)(C + idx) = make_float2(d0, d1);
                if (Crelu) *(float2*)(Crelu + idx) =
                               make_float2(fmaxf(d0, 0.f), fmaxf(d1, 0.f));
                if (Ch) {
                    __nv_bfloat16 h0 = __float2bfloat16(d0);
                    __nv_bfloat16 h1 = __float2bfloat16(d1);
                    ushort2 hs = make_ushort2(__bfloat16_as_ushort(h0),
                                              __bfloat16_as_ushort(h1));
                    ushort2 ls = make_ushort2(
                        __bfloat16_as_ushort(__float2bfloat16(d0 - __bfloat162float(h0))),
                        __bfloat16_as_ushort(__float2bfloat16(d1 - __bfloat162float(h1))));
                    *(ushort2*)(Ch + idx) = hs;
                    *(ushort2*)(Cl + idx) = ls;
                }
            }
        }
    }
}

// ----------------------------- elementwise ---------------------------------
__device__ __forceinline__ void split1(float x, unsigned short& h, unsigned short& l) {
    __nv_bfloat16 hb = __float2bfloat16(x);
    h = __bfloat16_as_ushort(hb);
    l = __bfloat16_as_ushort(__float2bfloat16(x - __bfloat162float(hb)));
}

__global__ void split_hl(const float* __restrict__ src,
                         unsigned short* __restrict__ h,
                         unsigned short* __restrict__ l, int n)
{
    int i = blockIdx.x * blockDim.x + threadIdx.x;
    if (i * 4 < n) {
        float4 v = *(const float4*)(src + i * 4);
        ushort4 hs, ls;
        split1(v.x, hs.x, ls.x); split1(v.y, hs.y, ls.y);
        split1(v.z, hs.z, ls.z); split1(v.w, hs.w, ls.w);
        *(ushort4*)(h + i * 4) = hs;
        *(ushort4*)(l + i * 4) = ls;
    }
}

__global__ void transpose_split(unsigned short* __restrict__ dh,
                                unsigned short* __restrict__ dl,
                                const float* __restrict__ src, int n)
{
    __shared__ float t[32][33];
    int x = blockIdx.x * 32 + threadIdx.x;
    int y = blockIdx.y * 32 + threadIdx.y;
    t[threadIdx.y][threadIdx.x] = src[(size_t)y * n + x];
    __syncthreads();
    int ox = blockIdx.y * 32 + threadIdx.x;
    int oy = blockIdx.x * 32 + threadIdx.y;
    unsigned short h, l;
    split1(t[threadIdx.x][threadIdx.y], h, l);
    dh[(size_t)oy * n + ox] = h;
    dl[(size_t)oy * n + ox] = l;
}

// dst = scale*src + diag*I, emitted as hi/lo bf16
__global__ void scale_diag_split(unsigned short* __restrict__ dh,
                                 unsigned short* __restrict__ dl,
                                 const float* __restrict__ src,
                                 float scale, float diag, int dim)
{
    int i = blockIdx.x * blockDim.x + threadIdx.x;
    if (i < dim * dim) {
        float v = scale * src[i];
        if ((i / dim) == (i % dim)) v += diag;
        unsigned short h, l;
        split1(v, h, l);
        dh[i] = h; dl[i] = l;
    }
}

// Ru = u + dt*b  (fp32 + hi/lo);  Rv = sv*v + (dt/eps)*relu(u)  (fp32)
__global__ void build_rhs_split(const float* __restrict__ u, const float* __restrict__ vbuf,
                                const float* __restrict__ b, float sv,
                                float* __restrict__ Ru,
                                unsigned short* __restrict__ Ruh,
                                unsigned short* __restrict__ Rul,
                                float* __restrict__ Rv, int n)
{
    int i = blockIdx.x * blockDim.x + threadIdx.x;
    if (i < n) {
        int col = i & (UNITS - 1);
        float uv = u[i];
        float ru = uv + 0.1f * b[col];
        Ru[i] = ru;
        unsigned short h, l;
        split1(ru, h, l);
        Ruh[i] = h; Rul[i] = l;
        Rv[i] = sv * vbuf[i] + 10.0f * fmaxf(uv, 0.0f);
    }
}

__global__ void softmax_rows(float* __restrict__ data, int cols)
{
    int row = blockIdx.x;
    float* d = data + (size_t)row * cols;
    __shared__ float sm[32];
    int tid = threadIdx.x, lane = tid & 31, warp = tid >> 5;
    int nwarp = blockDim.x >> 5;

    float m = -3.4e38f;
    for (int i = tid; i < cols; i += blockDim.x) m = fmaxf(m, d[i]);
#pragma unroll
    for (int o = 16; o; o >>= 1) m = fmaxf(m, __shfl_xor_sync(0xffffffffu, m, o));
    if (lane == 0) sm[warp] = m;
    __syncthreads();
    if (warp == 0) {
        float t = (lane < nwarp) ? sm[lane] : -3.4e38f;
#pragma unroll
        for (int o = 16; o; o >>= 1) t = fmaxf(t, __shfl_xor_sync(0xffffffffu, t, o));
        if (lane == 0) sm[0] = t;
    }
    __syncthreads();
    float mx = sm[0];
    __syncthreads();

    float s = 0.0f;
    for (int i = tid; i < cols; i += blockDim.x) {
        float e = expf(d[i] - mx);
        d[i] = e;
        s += e;
    }
#pragma unroll
    for (int o = 16; o; o >>= 1) s += __shfl_xor_sync(0xffffffffu, s, o);
    if (lane == 0) sm[warp] = s;
    __syncthreads();
    if (warp == 0) {
        float t = (lane < nwarp) ? sm[lane] : 0.0f;
#pragma unroll
        for (int o = 16; o; o >>= 1) t += __shfl_xor_sync(0xffffffffu, t, o);
        if (lane == 0) sm[0] = t;
    }
    __syncthreads();
    float inv = 1.0f / sm[0];
    for (int i = tid; i < cols; i += blockDim.x) d[i] *= inv;
}

// ---------------------------------------------------------------------------
extern "C" void kernel_launch(void* const* d_in, const int* in_sizes, int n_in,
                              void* d_out, int out_size)
{
    const float* x     = (const float*)d_in[0];
    const float* W_in  = (const float*)d_in[1];
    const float* b_in  = (const float*)d_in[2];
    const float* Ws[3] = {(const float*)d_in[3], (const float*)d_in[5], (const float*)d_in[7]};
    const float* bs[3] = {(const float*)d_in[4], (const float*)d_in[6], (const float*)d_in[8]};
    const float* W_out = (const float*)d_in[9];
    const float* b_out = (const float*)d_in[10];
    float* out = (float*)d_out;

    cudaFuncSetAttribute(gemm_tc, cudaFuncAttributeMaxDynamicSharedMemorySize, SMEM_GEMM);

    float *b0, *b1, *b2, *b3, *s1;
    cudaGetSymbolAddress((void**)&b0, g_b0);
    cudaGetSymbolAddress((void**)&b1, g_b1);
    cudaGetSymbolAddress((void**)&b2, g_b2);
    cudaGetSymbolAddress((void**)&b3, g_b3);
    cudaGetSymbolAddress((void**)&s1, g_s1);
    unsigned short *xh, *xl, *winh, *winl, *hah, *hal, *hbh, *hbl;
    unsigned short *wh, *wl, *s0h, *s0l, *mih, *mil, *woh, *wol;
    cudaGetSymbolAddress((void**)&xh, g_xh);   cudaGetSymbolAddress((void**)&xl, g_xl);
    cudaGetSymbolAddress((void**)&winh, g_winh); cudaGetSymbolAddress((void**)&winl, g_winl);
    cudaGetSymbolAddress((void**)&hah, g_hah); cudaGetSymbolAddress((void**)&hal, g_hal);
    cudaGetSymbolAddress((void**)&hbh, g_hbh); cudaGetSymbolAddress((void**)&hbl, g_hbl);
    cudaGetSymbolAddress((void**)&wh, g_wh);   cudaGetSymbolAddress((void**)&wl, g_wl);
    cudaGetSymbolAddress((void**)&s0h, g_s0h); cudaGetSymbolAddress((void**)&s0l, g_s0l);
    cudaGetSymbolAddress((void**)&mih, g_mih); cudaGetSymbolAddress((void**)&mil, g_mil);
    cudaGetSymbolAddress((void**)&woh, g_woh); cudaGetSymbolAddress((void**)&wol, g_wol);

    const int NB = BATCH * UNITS;
    dim3 gBig(UNITS / BN, BATCH / BM);                 // (8, 64)
    dim3 gSmall(UNITS / BN, UNITS / BM);               // (8, 8)
    dim3 gOut((OUTDIM + BN - 1) / BN, BATCH / BM);     // (8, 64)
    dim3 tblk(32, 32), tgrid(UNITS / 32, UNITS / 32);
    int ewBlocks = (NB + 255) / 256;
    int sdBlocks = (UNITS * UNITS + 255) / 256;

    // one-time splits of inputs
    split_hl<<<(BATCH * INDIM / 4 + 255) / 256, 256>>>(x, xh, xl, BATCH * INDIM);
    split_hl<<<(UNITS * INDIM / 4 + 255) / 256, 256>>>(W_in, winh, winl, UNITS * INDIM);
    split_hl<<<(OUTDIM * UNITS / 4 + 255) / 256, 256>>>(W_out, woh, wol, OUTDIM * UNITS);

    // z0 = x @ W_in^T + b_in -> b0 (u_in), relu(z0) -> b1 (v_in), fused
    gemm_tc<<<gBig, 256, SMEM_GEMM>>>(xh, xl, winh, winl, b0, b1, nullptr, nullptr,
                                      BATCH, UNITS, INDIM, 1.0f, b_in, 0.0f,
                                      nullptr, 0.0f);

    float* pu  = b0;
    float* pv  = b1;
    float* pru = b2;
    float* prv = b3;

    for (int l = 0; l < 3; ++l) {
        const float* W  = Ws[l];
        const float* bb = bs[l];
        float sv = (l == 0) ? 1.0f : -1.0f;

        transpose_split<<<tgrid, tblk>>>(s0h, s0l, W, UNITS);              // W^T
        split_hl<<<(UNITS * UNITS / 4 + 255) / 256, 256>>>(W, wh, wl, UNITS * UNITS);
        // K = W^T W   (fp32 only)
        gemm_tc<<<gSmall, 256, SMEM_GEMM>>>(s0h, s0l, s0h, s0l, s1, nullptr,
                                            nullptr, nullptr,
                                            UNITS, UNITS, UNITS, 1.0f, nullptr, 0.0f,
                                            nullptr, 0.0f);
        // Minv = (1/c)(I - aK)  [first-order Neumann], emitted as hi/lo
        scale_diag_split<<<sdBlocks, 256>>>(mih, mil, s1, -ACONST / CCONST,
                                            1.0f / CCONST, UNITS);

        build_rhs_split<<<ewBlocks, 256>>>(pu, pv, bb, sv, pru, hah, hal, prv, NB);
        // r = dt*Ru@W + Rv  (B = W^T); only splits needed downstream
        gemm_tc<<<gBig, 256, SMEM_GEMM>>>(hah, hal, s0h, s0l, nullptr, nullptr,
                                          hbh, hbl,
                                          BATCH, UNITS, UNITS, DT, nullptr, 0.0f,
                                          prv, 1.0f);
        // V = r @ Minv  (Minv symmetric -> NT ok)
        gemm_tc<<<gBig, 256, SMEM_GEMM>>>(hbh, hbl, mih, mil, prv, nullptr,
                                          hah, hal,
                                          BATCH, UNITS, UNITS, 1.0f, nullptr, 0.0f,
                                          nullptr, 0.0f);
        // u_out = dt*V@W^T - Ru ; splits only needed after the last layer
        gemm_tc<<<gBig, 256, SMEM_GEMM>>>(hah, hal, wh, wl, pu, nullptr,
                                          (l == 2) ? hbh : nullptr,
                                          (l == 2) ? hbl : nullptr,
                                          BATCH, UNITS, UNITS, DT, nullptr, 0.0f,
                                          pru, -1.0f);

        float* tmp = pv; pv = prv; prv = tmp;
    }

    // logits = u @ W_out^T + b_out -> out ; softmax
    gemm_tc<<<gOut, 256, SMEM_GEMM>>>(hbh, hbl, woh, wol, out, nullptr,
                                      nullptr, nullptr,
                                      BATCH, OUTDIM, UNITS, 1.0f, b_out, 0.0f,
                                      nullptr, 0.0f);
    softmax_rows<<<BATCH, 256>>>(out, OUTDIM);
}

// round 6
// speedup vs baseline: 3.2449x; 1.0086x over previous
#include <cuda_runtime.h>
#include <cuda_bf16.h>
#include <cstddef>
#include <cstdint>

// ---------------------------------------------------------------------------
// TransNet, mma.sync bf16 split-precision GEMM.
//   Layer solve:  v·(cI + dt^2 W^T W) = rhs_v + dt·rhs_u@W
//   u_out = -u = dt·v@W^T - rhs_u,  v_out = -v
//   (cI + dt^2 K)^{-1} ≈ (1/c)(I - aK)   [first-order Neumann, err ~1.5e-6]
// GEMMs NT: C[m,n] = sum_k A[m,k]*B[n,k] as AhBh + AlBh + AhBl (fp32 accum).
// 3-stage cp.async pipeline, 1 sync/chunk, ldmatrix + fragment double-buffer.
// ---------------------------------------------------------------------------

#define BATCH   8192
#define UNITS   1024
#define INDIM   2048
#define OUTDIM  1000

static const float DT     = 0.1f;
static const float CCONST = 11.0f;           // 1 + dt/eps
static const float ACONST = 0.01f / 11.0f;   // dt^2 / c

// ------------------------------- scratch (16B+ aligned) --------------------
__device__ __align__(256) float g_b0[BATCH * UNITS];
__device__ __align__(256) float g_b1[BATCH * UNITS];
__device__ __align__(256) float g_b2[BATCH * UNITS];
__device__ __align__(256) float g_b3[BATCH * UNITS];
__device__ __align__(256) float g_s1[UNITS * UNITS];   // K fp32

__device__ __align__(256) unsigned short g_xh[BATCH * INDIM];
__device__ __align__(256) unsigned short g_xl[BATCH * INDIM];
__device__ __align__(256) unsigned short g_winh[UNITS * INDIM];
__device__ __align__(256) unsigned short g_winl[UNITS * INDIM];
__device__ __align__(256) unsigned short g_hah[BATCH * UNITS];
__device__ __align__(256) unsigned short g_hal[BATCH * UNITS];
__device__ __align__(256) unsigned short g_hbh[BATCH * UNITS];
__device__ __align__(256) unsigned short g_hbl[BATCH * UNITS];
__device__ __align__(256) unsigned short g_wh[UNITS * UNITS];
__device__ __align__(256) unsigned short g_wl[UNITS * UNITS];
__device__ __align__(256) unsigned short g_s0h[UNITS * UNITS];
__device__ __align__(256) unsigned short g_s0l[UNITS * UNITS];
__device__ __align__(256) unsigned short g_mih[UNITS * UNITS];
__device__ __align__(256) unsigned short g_mil[UNITS * UNITS];
__device__ __align__(256) unsigned short g_woh[OUTDIM * UNITS];
__device__ __align__(256) unsigned short g_wol[OUTDIM * UNITS];

// ------------------------------ helpers ------------------------------------
#define SWZ(o) ((o) ^ (((o) >> 3) & 0x70u))

__device__ __forceinline__ uint32_t smem_u32(const void* p) {
    uint32_t a;
    asm("{ .reg .u64 t; cvta.to.shared.u64 t, %1; cvt.u32.u64 %0, t; }"
        : "=r"(a) : "l"(p));
    return a;
}

// cp.async 16B global->shared; src_sz=0 zero-fills (OOB rows)
__device__ __forceinline__ void cp16(uint32_t dst, const void* src, bool inb) {
    int sz = inb ? 16 : 0;
    asm volatile(
        "{\n\t.reg .u64 g;\n\tcvta.to.global.u64 g, %1;\n\t"
        "cp.async.cg.shared.global [%0], [g], 16, %2;\n\t}"
        :: "r"(dst), "l"(src), "r"(sz) : "memory");
}
__device__ __forceinline__ void cp_commit() {
    asm volatile("cp.async.commit_group;" ::: "memory");
}
__device__ __forceinline__ void cp_wait1() {
    asm volatile("cp.async.wait_group 1;" ::: "memory");
}

// mma.sync m16n8k16 row.col f32 <- bf16 x bf16 + f32
__device__ __forceinline__ void mma16816(float* d, const uint32_t* a, const uint32_t* b) {
    asm volatile(
        "mma.sync.aligned.m16n8k16.row.col.f32.bf16.bf16.f32 "
        "{%0,%1,%2,%3}, {%4,%5,%6,%7}, {%8,%9}, {%0,%1,%2,%3};"
        : "+f"(d[0]), "+f"(d[1]), "+f"(d[2]), "+f"(d[3])
        : "r"(a[0]), "r"(a[1]), "r"(a[2]), "r"(a[3]), "r"(b[0]), "r"(b[1]));
}

// ldmatrix x4: four 8x8 b16 matrices
__device__ __forceinline__ void ldsm4(uint32_t* r, uint32_t addr) {
    asm volatile("ldmatrix.sync.aligned.m8n8.x4.shared.b16 {%0,%1,%2,%3}, [%4];"
        : "=r"(r[0]), "=r"(r[1]), "=r"(r[2]), "=r"(r[3]) : "r"(addr));
}

// --------------------------- GEMM kernel -----------------------------------
// C[m,n] = alpha * sum_k A[m,k]B[n,k] (+bias[n]) (+add_scale*addp[m,n]) (+diag)
// Outputs optional: C fp32, Crelu fp32, (Ch, Cl) bf16 hi/lo split.
// A,B bf16 hi/lo pairs (K-major). M % 128 == 0, K % 64 == 0, N % 2 == 0.
#define BM 128
#define BN 128
#define BK 64
#define NSTAGE 3
#define TILE_B   (128 * 128)                  // bytes per operand tile
#define STAGE_B  (4 * TILE_B)                 // Ah, Al, Bh, Bl
#define SMEM_GEMM (1024 + NSTAGE * STAGE_B)   // 197632

__global__ __launch_bounds__(256) void gemm_tc(
    const unsigned short* __restrict__ Ah, const unsigned short* __restrict__ Al,
    const unsigned short* __restrict__ Bh, const unsigned short* __restrict__ Bl,
    float* __restrict__ C, float* __restrict__ Crelu,
    unsigned short* __restrict__ Ch, unsigned short* __restrict__ Cl,
    int M, int N, int K, float alpha,
    const float* __restrict__ bias, float diag_add,
    const float* __restrict__ addp, float add_scale)
{
    extern __shared__ char smem[];
    const uint32_t sbase = smem_u32(smem) + 1024;
    const int tid  = threadIdx.x;
    const int wid  = tid >> 5;
    const int lane = tid & 31;
    const int bm = blockIdx.y * BM;
    const int bn = blockIdx.x * BN;
    const int nc = K / BK;

    const unsigned short* srcs[4] = {Ah, Al, Bh, Bl};
    const int r0s[4] = {bm, bm, bn, bn};
    const int nrs[4] = {M, M, N, N};

    // per-thread fixed cp.async slot
    const int lrow = tid >> 3;            // 0..31
    const int lsc  = tid & 7;             // 16B column
    const uint32_t lswz_base = (uint32_t)lsc * 16u;

    auto issue_stage = [&](int c) {
        const int buf = c % NSTAGE;
        const int k0 = c * BK;
        const uint32_t sdst = sbase + buf * STAGE_B;
#pragma unroll
        for (int t = 0; t < 4; ++t) {
#pragma unroll
            for (int i = 0; i < 4; ++i) {
                int row = lrow + i * 32;
                uint32_t off = (uint32_t)row * 128u + lswz_base;
                cp16(sdst + t * TILE_B + SWZ(off),
                     srcs[t] + (size_t)(r0s[t] + row) * K + k0 + lsc * 8,
                     r0s[t] + row < nrs[t]);
            }
        }
        cp_commit();
    };

    // warp tiling: warp (wm, wn) owns rows [wm*32,+32) x cols [wn*64,+64)
    const int wm = wid & 3;
    const int wn = wid >> 2;
    const int r  = lane >> 2;
    const int c2 = (lane & 3) * 2;

    // ldmatrix per-lane addressing
    const int q   = lane >> 3;            // 0..3
    const int rin = lane & 7;             // row within 8
    const uint32_t a_row = (uint32_t)(wm * 32 + (q & 1) * 8 + rin) * 128u;
    const int a_sel = q >> 1;
    const uint32_t b_row = (uint32_t)(wn * 64 + (q >> 1) * 8 + rin) * 128u;
    const int b_sel = q & 1;

    float acc[2][8][4];
#pragma unroll
    for (int a = 0; a < 2; ++a)
#pragma unroll
        for (int b = 0; b < 8; ++b)
#pragma unroll
            for (int k = 0; k < 4; ++k) acc[a][b][k] = 0.0f;

    // fragment double buffers
    uint32_t ahf[2][2][4], alf[2][2][4], bhf[2][8][2], blf[2][8][2];
    uint32_t stg = 0;  // smem base of current stage (set per chunk)

    auto ldfrag = [&](int ks, int pb) {
        const uint32_t tAh = stg;
        const uint32_t tAl = stg + TILE_B;
        const uint32_t tBh = stg + 2 * TILE_B;
        const uint32_t tBl = stg + 3 * TILE_B;
        const uint32_t aoff = ((uint32_t)((ks * 2 + a_sel) ^ rin)) << 4;
        const uint32_t boff = ((uint32_t)((ks * 2 + b_sel) ^ rin)) << 4;
        ldsm4(ahf[pb][0], tAh + a_row + aoff);
        ldsm4(ahf[pb][1], tAh + a_row + 2048u + aoff);
        ldsm4(alf[pb][0], tAl + a_row + aoff);
        ldsm4(alf[pb][1], tAl + a_row + 2048u + aoff);
#pragma unroll
        for (int p = 0; p < 4; ++p) {
            uint32_t r4[4];
            ldsm4(r4, tBh + b_row + (uint32_t)p * 2048u + boff);
            bhf[pb][2 * p][0] = r4[0]; bhf[pb][2 * p][1] = r4[1];
            bhf[pb][2 * p + 1][0] = r4[2]; bhf[pb][2 * p + 1][1] = r4[3];
            ldsm4(r4, tBl + b_row + (uint32_t)p * 2048u + boff);
            blf[pb][2 * p][0] = r4[0]; blf[pb][2 * p][1] = r4[1];
            blf[pb][2 * p + 1][0] = r4[2]; blf[pb][2 * p + 1][1] = r4[3];
        }
    };

    issue_stage(0);
    if (nc > 1) issue_stage(1);

    for (int c = 0; c < nc; ++c) {
        cp_wait1();            // stage c complete
        __syncthreads();       // visible to all warps; stage (c-1)%3 free
        if (c + 2 < nc) issue_stage(c + 2);

        stg = sbase + (c % NSTAGE) * STAGE_B;
        ldfrag(0, 0);
#pragma unroll
        for (int ks = 0; ks < 4; ++ks) {
            const int cur = ks & 1;
            if (ks < 3) ldfrag(ks + 1, cur ^ 1);
#pragma unroll
            for (int nt = 0; nt < 8; ++nt) {
                mma16816(acc[0][nt], ahf[cur][0], bhf[cur][nt]);
                mma16816(acc[1][nt], ahf[cur][1], bhf[cur][nt]);
            }
#pragma unroll
            for (int nt = 0; nt < 8; ++nt) {
                mma16816(acc[0][nt], alf[cur][0], bhf[cur][nt]);
                mma16816(acc[1][nt], alf[cur][1], bhf[cur][nt]);
            }
#pragma unroll
            for (int nt = 0; nt < 8; ++nt) {
                mma16816(acc[0][nt], ahf[cur][0], blf[cur][nt]);
                mma16816(acc[1][nt], ahf[cur][1], blf[cur][nt]);
            }
        }
    }
    __syncthreads();

    // epilogue
#pragma unroll
    for (int mt = 0; mt < 2; ++mt) {
#pragma unroll
        for (int nt = 0; nt < 8; ++nt) {
            const int col = bn + wn * 64 + nt * 8 + c2;
            if (col >= N) continue;
            float bx = 0.f, by = 0.f;
            if (bias) { bx = bias[col]; by = bias[col + 1]; }
#pragma unroll
            for (int h = 0; h < 2; ++h) {
                const int m = bm + wm * 32 + mt * 16 + r + h * 8;
                float d0 = alpha * acc[mt][nt][2 * h + 0] + bx;
                float d1 = alpha * acc[mt][nt][2 * h + 1] + by;
                size_t idx = (size_t)m * N + col;
                if (addp) {
                    d0 += add_scale * addp[idx];
                    d1 += add_scale * addp[idx + 1];
                }
                if (diag_add != 0.0f) {
                    if (m == col)     d0 += diag_add;
                    if (m == col + 1) d1 += diag_add;
                }
                if (C)     *(float2*)(C + idx) = make_float2(d0, d1);
                if (Crelu) *(float2*)(Crelu + idx) =
                               make_float2(fmaxf(d0, 0.f), fmaxf(d1, 0.f));
                if (Ch) {
                    __nv_bfloat16 h0 = __float2bfloat16(d0);
                    __nv_bfloat16 h1 = __float2bfloat16(d1);
                    ushort2 hs = make_ushort2(__bfloat16_as_ushort(h0),
                                              __bfloat16_as_ushort(h1));
                    ushort2 ls = make_ushort2(
                        __bfloat16_as_ushort(__float2bfloat16(d0 - __bfloat162float(h0))),
                        __bfloat16_as_ushort(__float2bfloat16(d1 - __bfloat162float(h1))));
                    *(ushort2*)(Ch + idx) = hs;
                    *(ushort2*)(Cl + idx) = ls;
                }
            }
        }
    }
}

// ----------------------------- elementwise ---------------------------------
__device__ __forceinline__ void split1(float x, unsigned short& h, unsigned short& l) {
    __nv_bfloat16 hb = __float2bfloat16(x);
    h = __bfloat16_as_ushort(hb);
    l = __bfloat16_as_ushort(__float2bfloat16(x - __bfloat162float(hb)));
}

__global__ void split_hl(const float* __restrict__ src,
                         unsigned short* __restrict__ h,
                         unsigned short* __restrict__ l, int n)
{
    int i = blockIdx.x * blockDim.x + threadIdx.x;
    if (i * 4 < n) {
        float4 v = *(const float4*)(src + i * 4);
        ushort4 hs, ls;
        split1(v.x, hs.x, ls.x); split1(v.y, hs.y, ls.y);
        split1(v.z, hs.z, ls.z); split1(v.w, hs.w, ls.w);
        *(ushort4*)(h + i * 4) = hs;
        *(ushort4*)(l + i * 4) = ls;
    }
}

// one pass over W: direct split -> (wh, wl); transposed split -> (th, tl)
__global__ void weight_split_both(unsigned short* __restrict__ wh,
                                  unsigned short* __restrict__ wl,
                                  unsigned short* __restrict__ th,
                                  unsigned short* __restrict__ tl,
                                  const float* __restrict__ W, int n)
{
    __shared__ float t[32][33];
    int x = blockIdx.x * 32 + threadIdx.x;
    int y = blockIdx.y * 32 + threadIdx.y;
    float v = W[(size_t)y * n + x];
    t[threadIdx.y][threadIdx.x] = v;
    unsigned short h, l;
    split1(v, h, l);
    wh[(size_t)y * n + x] = h;
    wl[(size_t)y * n + x] = l;
    __syncthreads();
    int ox = blockIdx.y * 32 + threadIdx.x;
    int oy = blockIdx.x * 32 + threadIdx.y;
    split1(t[threadIdx.x][threadIdx.y], h, l);
    th[(size_t)oy * n + ox] = h;
    tl[(size_t)oy * n + ox] = l;
}

// dst = scale*src + diag*I, emitted as hi/lo bf16
__global__ void scale_diag_split(unsigned short* __restrict__ dh,
                                 unsigned short* __restrict__ dl,
                                 const float* __restrict__ src,
                                 float scale, float diag, int dim)
{
    int i = blockIdx.x * blockDim.x + threadIdx.x;
    if (i < dim * dim) {
        float v = scale * src[i];
        if ((i / dim) == (i % dim)) v += diag;
        unsigned short h, l;
        split1(v, h, l);
        dh[i] = h; dl[i] = l;
    }
}

// Ru = u + dt*b  (fp32 + hi/lo);  Rv = sv*v + (dt/eps)*relu(u)  (fp32)
__global__ void build_rhs_split(const float* __restrict__ u, const float* __restrict__ vbuf,
                                const float* __restrict__ b, float sv,
                                float* __restrict__ Ru,
                                unsigned short* __restrict__ Ruh,
                                unsigned short* __restrict__ Rul,
                                float* __restrict__ Rv, int n)
{
    int i = blockIdx.x * blockDim.x + threadIdx.x;
    if (i < n) {
        int col = i & (UNITS - 1);
        float uv = u[i];
        float ru = uv + 0.1f * b[col];
        Ru[i] = ru;
        unsigned short h, l;
        split1(ru, h, l);
        Ruh[i] = h; Rul[i] = l;
        Rv[i] = sv * vbuf[i] + 10.0f * fmaxf(uv, 0.0f);
    }
}

__global__ void softmax_rows(float* __restrict__ data, int cols)
{
    int row = blockIdx.x;
    float* d = data + (size_t)row * cols;
    __shared__ float sm[32];
    int tid = threadIdx.x, lane = tid & 31, warp = tid >> 5;
    int nwarp = blockDim.x >> 5;

    float m = -3.4e38f;
    for (int i = tid; i < cols; i += blockDim.x) m = fmaxf(m, d[i]);
#pragma unroll
    for (int o = 16; o; o >>= 1) m = fmaxf(m, __shfl_xor_sync(0xffffffffu, m, o));
    if (lane == 0) sm[warp] = m;
    __syncthreads();
    if (warp == 0) {
        float t = (lane < nwarp) ? sm[lane] : -3.4e38f;
#pragma unroll
        for (int o = 16; o; o >>= 1) t = fmaxf(t, __shfl_xor_sync(0xffffffffu, t, o));
        if (lane == 0) sm[0] = t;
    }
    __syncthreads();
    float mx = sm[0];
    __syncthreads();

    float s = 0.0f;
    for (int i = tid; i < cols; i += blockDim.x) {
        float e = expf(d[i] - mx);
        d[i] = e;
        s += e;
    }
#pragma unroll
    for (int o = 16; o; o >>= 1) s += __shfl_xor_sync(0xffffffffu, s, o);
    if (lane == 0) sm[warp] = s;
    __syncthreads();
    if (warp == 0) {
        float t = (lane < nwarp) ? sm[lane] : 0.0f;
#pragma unroll
        for (int o = 16; o; o >>= 1) t += __shfl_xor_sync(0xffffffffu, t, o);
        if (lane == 0) sm[0] = t;
    }
    __syncthreads();
    float inv = 1.0f / sm[0];
    for (int i = tid; i < cols; i += blockDim.x) d[i] *= inv;
}

// ---------------------------------------------------------------------------
extern "C" void kernel_launch(void* const* d_in, const int* in_sizes, int n_in,
                              void* d_out, int out_size)
{
    const float* x     = (const float*)d_in[0];
    const float* W_in  = (const float*)d_in[1];
    const float* b_in  = (const float*)d_in[2];
    const float* Ws[3] = {(const float*)d_in[3], (const float*)d_in[5], (const float*)d_in[7]};
    const float* bs[3] = {(const float*)d_in[4], (const float*)d_in[6], (const float*)d_in[8]};
    const float* W_out = (const float*)d_in[9];
    const float* b_out = (const float*)d_in[10];
    float* out = (float*)d_out;

    cudaFuncSetAttribute(gemm_tc, cudaFuncAttributeMaxDynamicSharedMemorySize, SMEM_GEMM);

    float *b0, *b1, *b2, *b3, *s1;
    cudaGetSymbolAddress((void**)&b0, g_b0);
    cudaGetSymbolAddress((void**)&b1, g_b1);
    cudaGetSymbolAddress((void**)&b2, g_b2);
    cudaGetSymbolAddress((void**)&b3, g_b3);
    cudaGetSymbolAddress((void**)&s1, g_s1);
    unsigned short *xh, *xl, *winh, *winl, *hah, *hal, *hbh, *hbl;
    unsigned short *wh, *wl, *s0h, *s0l, *mih, *mil, *woh, *wol;
    cudaGetSymbolAddress((void**)&xh, g_xh);   cudaGetSymbolAddress((void**)&xl, g_xl);
    cudaGetSymbolAddress((void**)&winh, g_winh); cudaGetSymbolAddress((void**)&winl, g_winl);
    cudaGetSymbolAddress((void**)&hah, g_hah); cudaGetSymbolAddress((void**)&hal, g_hal);
    cudaGetSymbolAddress((void**)&hbh, g_hbh); cudaGetSymbolAddress((void**)&hbl, g_hbl);
    cudaGetSymbolAddress((void**)&wh, g_wh);   cudaGetSymbolAddress((void**)&wl, g_wl);
    cudaGetSymbolAddress((void**)&s0h, g_s0h); cudaGetSymbolAddress((void**)&s0l, g_s0l);
    cudaGetSymbolAddress((void**)&mih, g_mih); cudaGetSymbolAddress((void**)&mil, g_mil);
    cudaGetSymbolAddress((void**)&woh, g_woh); cudaGetSymbolAddress((void**)&wol, g_wol);

    const int NB = BATCH * UNITS;
    dim3 gBig(UNITS / BN, BATCH / BM);                 // (8, 64)
    dim3 gSmall(UNITS / BN, UNITS / BM);               // (8, 8)
    dim3 gOut((OUTDIM + BN - 1) / BN, BATCH / BM);     // (8, 64)
    dim3 tblk(32, 32), tgrid(UNITS / 32, UNITS / 32);
    int ewBlocks = (NB + 255) / 256;
    int sdBlocks = (UNITS * UNITS + 255) / 256;

    // one-time splits of inputs
    split_hl<<<(BATCH * INDIM / 4 + 255) / 256, 256>>>(x, xh, xl, BATCH * INDIM);
    split_hl<<<(UNITS * INDIM / 4 + 255) / 256, 256>>>(W_in, winh, winl, UNITS * INDIM);
    split_hl<<<(OUTDIM * UNITS / 4 + 255) / 256, 256>>>(W_out, woh, wol, OUTDIM * UNITS);

    // z0 = x @ W_in^T + b_in -> b0 (u_in), relu(z0) -> b1 (v_in), fused
    gemm_tc<<<gBig, 256, SMEM_GEMM>>>(xh, xl, winh, winl, b0, b1, nullptr, nullptr,
                                      BATCH, UNITS, INDIM, 1.0f, b_in, 0.0f,
                                      nullptr, 0.0f);

    float* pu  = b0;
    float* pv  = b1;
    float* pru = b2;
    float* prv = b3;

    for (int l = 0; l < 3; ++l) {
        const float* W  = Ws[l];
        const float* bb = bs[l];
        float sv = (l == 0) ? 1.0f : -1.0f;

        // W -> (wh, wl) and W^T -> (s0h, s0l), one read of W
        weight_split_both<<<tgrid, tblk>>>(wh, wl, s0h, s0l, W, UNITS);
        // K = W^T W   (fp32 only)
        gemm_tc<<<gSmall, 256, SMEM_GEMM>>>(s0h, s0l, s0h, s0l, s1, nullptr,
                                            nullptr, nullptr,
                                            UNITS, UNITS, UNITS, 1.0f, nullptr, 0.0f,
                                            nullptr, 0.0f);
        // Minv = (1/c)(I - aK)  [first-order Neumann], emitted as hi/lo
        scale_diag_split<<<sdBlocks, 256>>>(mih, mil, s1, -ACONST / CCONST,
                                            1.0f / CCONST, UNITS);

        build_rhs_split<<<ewBlocks, 256>>>(pu, pv, bb, sv, pru, hah, hal, prv, NB);
        // r = dt*Ru@W + Rv  (B = W^T); only splits needed downstream
        gemm_tc<<<gBig, 256, SMEM_GEMM>>>(hah, hal, s0h, s0l, nullptr, nullptr,
                                          hbh, hbl,
                                          BATCH, UNITS, UNITS, DT, nullptr, 0.0f,
                                          prv, 1.0f);
        // V = r @ Minv  (Minv symmetric -> NT ok)
        gemm_tc<<<gBig, 256, SMEM_GEMM>>>(hbh, hbl, mih, mil, prv, nullptr,
                                          hah, hal,
                                          BATCH, UNITS, UNITS, 1.0f, nullptr, 0.0f,
                                          nullptr, 0.0f);
        // u_out = dt*V@W^T - Ru ; splits only needed after the last layer
        gemm_tc<<<gBig, 256, SMEM_GEMM>>>(hah, hal, wh, wl, pu, nullptr,
                                          (l == 2) ? hbh : nullptr,
                                          (l == 2) ? hbl : nullptr,
                                          BATCH, UNITS, UNITS, DT, nullptr, 0.0f,
                                          pru, -1.0f);

        float* tmp = pv; pv = prv; prv = tmp;
    }

    // logits = u @ W_out^T + b_out -> out ; softmax
    gemm_tc<<<gOut, 256, SMEM_GEMM>>>(hbh, hbl, woh, wol, out, nullptr,
                                      nullptr, nullptr,
                                      BATCH, OUTDIM, UNITS, 1.0f, b_out, 0.0f,
                                      nullptr, 0.0f);
    softmax_rows<<<BATCH, 256>>>(out, OUTDIM);
}

// round 7
// speedup vs baseline: 3.6539x; 1.1261x over previous
#include <cuda_runtime.h>
#include <cuda_bf16.h>
#include <cstddef>
#include <cstdint>

// ---------------------------------------------------------------------------
// TransNet, mma.sync bf16 split-precision GEMM, 2 CTAs/SM occupancy build.
//   Layer solve:  v·(cI + dt^2 W^T W) = rhs_v + dt·rhs_u@W
//   u_out = -u = dt·v@W^T - rhs_u,  v_out = -v
//   (cI + dt^2 K)^{-1} ≈ (1/c)(I - aK)   [first-order Neumann, err ~1.5e-6]
// GEMMs NT: C[m,n] = sum_k A[m,k]*B[n,k] as AhBh + AlBh + AhBl (fp32 accum).
// BK=32 (64B rows), 3-stage cp.async, warp tile 32x32, <=128 regs, 2 CTA/SM.
// ---------------------------------------------------------------------------

#define BATCH   8192
#define UNITS   1024
#define INDIM   2048
#define OUTDIM  1000

static const float DT     = 0.1f;
static const float CCONST = 11.0f;           // 1 + dt/eps
static const float ACONST = 0.01f / 11.0f;   // dt^2 / c

// ------------------------------- scratch (16B+ aligned) --------------------
__device__ __align__(256) float g_b0[BATCH * UNITS];
__device__ __align__(256) float g_b1[BATCH * UNITS];
__device__ __align__(256) float g_b2[BATCH * UNITS];
__device__ __align__(256) float g_b3[BATCH * UNITS];
__device__ __align__(256) float g_s1[UNITS * UNITS];   // K fp32

__device__ __align__(256) unsigned short g_xh[BATCH * INDIM];
__device__ __align__(256) unsigned short g_xl[BATCH * INDIM];
__device__ __align__(256) unsigned short g_winh[UNITS * INDIM];
__device__ __align__(256) unsigned short g_winl[UNITS * INDIM];
__device__ __align__(256) unsigned short g_hah[BATCH * UNITS];
__device__ __align__(256) unsigned short g_hal[BATCH * UNITS];
__device__ __align__(256) unsigned short g_hbh[BATCH * UNITS];
__device__ __align__(256) unsigned short g_hbl[BATCH * UNITS];
__device__ __align__(256) unsigned short g_wh[UNITS * UNITS];
__device__ __align__(256) unsigned short g_wl[UNITS * UNITS];
__device__ __align__(256) unsigned short g_s0h[UNITS * UNITS];
__device__ __align__(256) unsigned short g_s0l[UNITS * UNITS];
__device__ __align__(256) unsigned short g_mih[UNITS * UNITS];
__device__ __align__(256) unsigned short g_mil[UNITS * UNITS];
__device__ __align__(256) unsigned short g_woh[OUTDIM * UNITS];
__device__ __align__(256) unsigned short g_wol[OUTDIM * UNITS];

// ------------------------------ helpers ------------------------------------
__device__ __forceinline__ uint32_t smem_u32(const void* p) {
    uint32_t a;
    asm("{ .reg .u64 t; cvta.to.shared.u64 t, %1; cvt.u32.u64 %0, t; }"
        : "=r"(a) : "l"(p));
    return a;
}

// cp.async 16B global->shared; src_sz=0 zero-fills (OOB rows)
__device__ __forceinline__ void cp16(uint32_t dst, const void* src, bool inb) {
    int sz = inb ? 16 : 0;
    asm volatile(
        "{\n\t.reg .u64 g;\n\tcvta.to.global.u64 g, %1;\n\t"
        "cp.async.cg.shared.global [%0], [g], 16, %2;\n\t}"
        :: "r"(dst), "l"(src), "r"(sz) : "memory");
}
__device__ __forceinline__ void cp_commit() {
    asm volatile("cp.async.commit_group;" ::: "memory");
}
__device__ __forceinline__ void cp_wait1() {
    asm volatile("cp.async.wait_group 1;" ::: "memory");
}

// mma.sync m16n8k16 row.col f32 <- bf16 x bf16 + f32
__device__ __forceinline__ void mma16816(float* d, const uint32_t* a, const uint32_t* b) {
    asm volatile(
        "mma.sync.aligned.m16n8k16.row.col.f32.bf16.bf16.f32 "
        "{%0,%1,%2,%3}, {%4,%5,%6,%7}, {%8,%9}, {%0,%1,%2,%3};"
        : "+f"(d[0]), "+f"(d[1]), "+f"(d[2]), "+f"(d[3])
        : "r"(a[0]), "r"(a[1]), "r"(a[2]), "r"(a[3]), "r"(b[0]), "r"(b[1]));
}

// ldmatrix x4: four 8x8 b16 matrices
__device__ __forceinline__ void ldsm4(uint32_t* r, uint32_t addr) {
    asm volatile("ldmatrix.sync.aligned.m8n8.x4.shared.b16 {%0,%1,%2,%3}, [%4];"
        : "=r"(r[0]), "=r"(r[1]), "=r"(r[2]), "=r"(r[3]) : "r"(addr));
}

// --------------------------- GEMM kernel -----------------------------------
// C[m,n] = alpha * sum_k A[m,k]B[n,k] (+bias[n]) (+add_scale*addp[m,n]) (+diag)
// Outputs optional: C fp32, Crelu fp32, (Ch, Cl) bf16 hi/lo split.
// A,B bf16 hi/lo pairs (K-major). M % 128 == 0, K % 32 == 0, N % 2 == 0.
// Tiles: BM=128, BN=64, BK=32. Rows are 64B; swizzle chunk ^= (row>>1)&3.
#define BM 128
#define BN 64
#define BK 32
#define A_TILE_B (128 * 64)                   // 8192 B
#define B_TILE_B (64 * 64)                    // 4096 B
#define STAGE_B  (2 * A_TILE_B + 2 * B_TILE_B) // 24576 B
#define NSTAGE 3
#define SMEM_GEMM (1024 + NSTAGE * STAGE_B)   // 74752

__global__ __launch_bounds__(256, 2) void gemm_tc(
    const unsigned short* __restrict__ Ah, const unsigned short* __restrict__ Al,
    const unsigned short* __restrict__ Bh, const unsigned short* __restrict__ Bl,
    float* __restrict__ C, float* __restrict__ Crelu,
    unsigned short* __restrict__ Ch, unsigned short* __restrict__ Cl,
    int M, int N, int K, float alpha,
    const float* __restrict__ bias, float diag_add,
    const float* __restrict__ addp, float add_scale)
{
    extern __shared__ char smem[];
    const uint32_t sbase = smem_u32(smem) + 1024;
    const int tid  = threadIdx.x;
    const int wid  = tid >> 5;
    const int lane = tid & 31;
    const int bm = blockIdx.y * BM;
    const int bn = blockIdx.x * BN;
    const int nc = K / BK;

    auto issue_stage = [&](int c) {
        const int k0 = c * BK;
        const uint32_t sd = sbase + (c % NSTAGE) * STAGE_B;
        // A tiles: 128 rows x 4 chunks = 512 slots -> 2 passes of 256
#pragma unroll
        for (int t = 0; t < 2; ++t) {
            const unsigned short* src = t ? Al : Ah;
            const uint32_t tb = sd + t * A_TILE_B;
#pragma unroll
            for (int p = 0; p < 2; ++p) {
                int s   = tid + p * 256;
                int row = s >> 2, ch = s & 3;
                uint32_t addr = tb + (uint32_t)row * 64u
                              + (uint32_t)((ch ^ ((row >> 1) & 3)) << 4);
                cp16(addr, src + (size_t)(bm + row) * K + k0 + ch * 8,
                     bm + row < M);
            }
        }
        // B tiles: 64 rows x 4 chunks = 256 slots -> 1 pass
#pragma unroll
        for (int t = 0; t < 2; ++t) {
            const unsigned short* src = t ? Bl : Bh;
            const uint32_t tb = sd + 2 * A_TILE_B + t * B_TILE_B;
            int row = tid >> 2, ch = tid & 3;
            uint32_t addr = tb + (uint32_t)row * 64u
                          + (uint32_t)((ch ^ ((row >> 1) & 3)) << 4);
            cp16(addr, src + (size_t)(bn + row) * K + k0 + ch * 8,
                 bn + row < N);
        }
        cp_commit();
    };

    // warp tiling: warp (wm, wn) owns rows [wm*32,+32) x cols [wn*32,+32)
    const int wm = wid & 3;
    const int wn = wid >> 2;
    const int r  = lane >> 2;
    const int c2 = (lane & 3) * 2;

    // ldmatrix per-lane addressing
    const int q    = lane >> 3;           // 0..3 (matrix id)
    const int rin  = lane & 7;
    const int rsw  = rin >> 1;            // swizzle selector
    const uint32_t a_row = (uint32_t)(wm * 32 + (q & 1) * 8 + rin) * 64u;
    const int a_sel = q >> 1;
    const uint32_t b_row = (uint32_t)(wn * 32 + (q >> 1) * 8 + rin) * 64u;
    const int b_sel = q & 1;

    float acc[2][4][4];
#pragma unroll
    for (int a = 0; a < 2; ++a)
#pragma unroll
        for (int b = 0; b < 4; ++b)
#pragma unroll
            for (int k = 0; k < 4; ++k) acc[a][b][k] = 0.0f;

    issue_stage(0);
    if (nc > 1) issue_stage(1);

    for (int c = 0; c < nc; ++c) {
        cp_wait1();
        __syncthreads();
        if (c + 2 < nc) issue_stage(c + 2);

        const uint32_t tAh = sbase + (c % NSTAGE) * STAGE_B;
        const uint32_t tAl = tAh + A_TILE_B;
        const uint32_t tBh = tAh + 2 * A_TILE_B;
        const uint32_t tBl = tBh + B_TILE_B;

#pragma unroll
        for (int ks = 0; ks < 2; ++ks) {
            const uint32_t aoff = (uint32_t)(((ks * 2 + a_sel) ^ rsw)) << 4;
            const uint32_t boff = (uint32_t)(((ks * 2 + b_sel) ^ rsw)) << 4;

            uint32_t ah[2][4], al[2][4];
            ldsm4(ah[0], tAh + a_row + aoff);
            ldsm4(ah[1], tAh + a_row + 1024u + aoff);   // +16 rows
            ldsm4(al[0], tAl + a_row + aoff);
            ldsm4(al[1], tAl + a_row + 1024u + aoff);

            uint32_t bh[4][2], bl[4][2];
#pragma unroll
            for (int p = 0; p < 2; ++p) {
                uint32_t r4[4];
                ldsm4(r4, tBh + b_row + (uint32_t)p * 1024u + boff);
                bh[2 * p][0] = r4[0]; bh[2 * p][1] = r4[1];
                bh[2 * p + 1][0] = r4[2]; bh[2 * p + 1][1] = r4[3];
                ldsm4(r4, tBl + b_row + (uint32_t)p * 1024u + boff);
                bl[2 * p][0] = r4[0]; bl[2 * p][1] = r4[1];
                bl[2 * p + 1][0] = r4[2]; bl[2 * p + 1][1] = r4[3];
            }

#pragma unroll
            for (int nt = 0; nt < 4; ++nt) {
                mma16816(acc[0][nt], ah[0], bh[nt]);
                mma16816(acc[1][nt], ah[1], bh[nt]);
            }
#pragma unroll
            for (int nt = 0; nt < 4; ++nt) {
                mma16816(acc[0][nt], al[0], bh[nt]);
                mma16816(acc[1][nt], al[1], bh[nt]);
            }
#pragma unroll
            for (int nt = 0; nt < 4; ++nt) {
                mma16816(acc[0][nt], ah[0], bl[nt]);
                mma16816(acc[1][nt], ah[1], bl[nt]);
            }
        }
    }
    __syncthreads();

    // epilogue
#pragma unroll
    for (int mt = 0; mt < 2; ++mt) {
#pragma unroll
        for (int nt = 0; nt < 4; ++nt) {
            const int col = bn + wn * 32 + nt * 8 + c2;
            if (col >= N) continue;
            float bx = 0.f, by = 0.f;
            if (bias) { bx = bias[col]; by = bias[col + 1]; }
#pragma unroll
            for (int h = 0; h < 2; ++h) {
                const int m = bm + wm * 32 + mt * 16 + r + h * 8;
                float d0 = alpha * acc[mt][nt][2 * h + 0] + bx;
                float d1 = alpha * acc[mt][nt][2 * h + 1] + by;
                size_t idx = (size_t)m * N + col;
                if (addp) {
                    d0 += add_scale * addp[idx];
                    d1 += add_scale * addp[idx + 1];
                }
                if (diag_add != 0.0f) {
                    if (m == col)     d0 += diag_add;
                    if (m == col + 1) d1 += diag_add;
                }
                if (C)     *(float2*)(C + idx) = make_float2(d0, d1);
                if (Crelu) *(float2*)(Crelu + idx) =
                               make_float2(fmaxf(d0, 0.f), fmaxf(d1, 0.f));
                if (Ch) {
                    __nv_bfloat16 h0 = __float2bfloat16(d0);
                    __nv_bfloat16 h1 = __float2bfloat16(d1);
                    ushort2 hs = make_ushort2(__bfloat16_as_ushort(h0),
                                              __bfloat16_as_ushort(h1));
                    ushort2 ls = make_ushort2(
                        __bfloat16_as_ushort(__float2bfloat16(d0 - __bfloat162float(h0))),
                        __bfloat16_as_ushort(__float2bfloat16(d1 - __bfloat162float(h1))));
                    *(ushort2*)(Ch + idx) = hs;
                    *(ushort2*)(Cl + idx) = ls;
                }
            }
        }
    }
}

// ----------------------------- elementwise ---------------------------------
__device__ __forceinline__ void split1(float x, unsigned short& h, unsigned short& l) {
    __nv_bfloat16 hb = __float2bfloat16(x);
    h = __bfloat16_as_ushort(hb);
    l = __bfloat16_as_ushort(__float2bfloat16(x - __bfloat162float(hb)));
}

__global__ void split_hl(const float* __restrict__ src,
                         unsigned short* __restrict__ h,
                         unsigned short* __restrict__ l, int n)
{
    int i = blockIdx.x * blockDim.x + threadIdx.x;
    if (i * 4 < n) {
        float4 v = *(const float4*)(src + i * 4);
        ushort4 hs, ls;
        split1(v.x, hs.x, ls.x); split1(v.y, hs.y, ls.y);
        split1(v.z, hs.z, ls.z); split1(v.w, hs.w, ls.w);
        *(ushort4*)(h + i * 4) = hs;
        *(ushort4*)(l + i * 4) = ls;
    }
}

// one pass over W: direct split -> (wh, wl); transposed split -> (th, tl)
__global__ void weight_split_both(unsigned short* __restrict__ wh,
                                  unsigned short* __restrict__ wl,
                                  unsigned short* __restrict__ th,
                                  unsigned short* __restrict__ tl,
                                  const float* __restrict__ W, int n)
{
    __shared__ float t[32][33];
    int x = blockIdx.x * 32 + threadIdx.x;
    int y = blockIdx.y * 32 + threadIdx.y;
    float v = W[(size_t)y * n + x];
    t[threadIdx.y][threadIdx.x] = v;
    unsigned short h, l;
    split1(v, h, l);
    wh[(size_t)y * n + x] = h;
    wl[(size_t)y * n + x] = l;
    __syncthreads();
    int ox = blockIdx.y * 32 + threadIdx.x;
    int oy = blockIdx.x * 32 + threadIdx.y;
    split1(t[threadIdx.x][threadIdx.y], h, l);
    th[(size_t)oy * n + ox] = h;
    tl[(size_t)oy * n + ox] = l;
}

// dst = scale*src + diag*I, emitted as hi/lo bf16
__global__ void scale_diag_split(unsigned short* __restrict__ dh,
                                 unsigned short* __restrict__ dl,
                                 const float* __restrict__ src,
                                 float scale, float diag, int dim)
{
    int i = blockIdx.x * blockDim.x + threadIdx.x;
    if (i < dim * dim) {
        float v = scale * src[i];
        if ((i / dim) == (i % dim)) v += diag;
        unsigned short h, l;
        split1(v, h, l);
        dh[i] = h; dl[i] = l;
    }
}

// Ru = u + dt*b  (fp32 + hi/lo);  Rv = sv*v + (dt/eps)*relu(u)  (fp32)
__global__ void build_rhs_split(const float* __restrict__ u, const float* __restrict__ vbuf,
                                const float* __restrict__ b, float sv,
                                float* __restrict__ Ru,
                                unsigned short* __restrict__ Ruh,
                                unsigned short* __restrict__ Rul,
                                float* __restrict__ Rv, int n)
{
    int i = blockIdx.x * blockDim.x + threadIdx.x;
    if (i < n) {
        int col = i & (UNITS - 1);
        float uv = u[i];
        float ru = uv + 0.1f * b[col];
        Ru[i] = ru;
        unsigned short h, l;
        split1(ru, h, l);
        Ruh[i] = h; Rul[i] = l;
        Rv[i] = sv * vbuf[i] + 10.0f * fmaxf(uv, 0.0f);
    }
}

__global__ void softmax_rows(float* __restrict__ data, int cols)
{
    int row = blockIdx.x;
    float* d = data + (size_t)row * cols;
    __shared__ float sm[32];
    int tid = threadIdx.x, lane = tid & 31, warp = tid >> 5;
    int nwarp = blockDim.x >> 5;

    float m = -3.4e38f;
    for (int i = tid; i < cols; i += blockDim.x) m = fmaxf(m, d[i]);
#pragma unroll
    for (int o = 16; o; o >>= 1) m = fmaxf(m, __shfl_xor_sync(0xffffffffu, m, o));
    if (lane == 0) sm[warp] = m;
    __syncthreads();
    if (warp == 0) {
        float t = (lane < nwarp) ? sm[lane] : -3.4e38f;
#pragma unroll
        for (int o = 16; o; o >>= 1) t = fmaxf(t, __shfl_xor_sync(0xffffffffu, t, o));
        if (lane == 0) sm[0] = t;
    }
    __syncthreads();
    float mx = sm[0];
    __syncthreads();

    float s = 0.0f;
    for (int i = tid; i < cols; i += blockDim.x) {
        float e = expf(d[i] - mx);
        d[i] = e;
        s += e;
    }
#pragma unroll
    for (int o = 16; o; o >>= 1) s += __shfl_xor_sync(0xffffffffu, s, o);
    if (lane == 0) sm[warp] = s;
    __syncthreads();
    if (warp == 0) {
        float t = (lane < nwarp) ? sm[lane] : 0.0f;
#pragma unroll
        for (int o = 16; o; o >>= 1) t += __shfl_xor_sync(0xffffffffu, t, o);
        if (lane == 0) sm[0] = t;
    }
    __syncthreads();
    float inv = 1.0f / sm[0];
    for (int i = tid; i < cols; i += blockDim.x) d[i] *= inv;
}

// ---------------------------------------------------------------------------
extern "C" void kernel_launch(void* const* d_in, const int* in_sizes, int n_in,
                              void* d_out, int out_size)
{
    const float* x     = (const float*)d_in[0];
    const float* W_in  = (const float*)d_in[1];
    const float* b_in  = (const float*)d_in[2];
    const float* Ws[3] = {(const float*)d_in[3], (const float*)d_in[5], (const float*)d_in[7]};
    const float* bs[3] = {(const float*)d_in[4], (const float*)d_in[6], (const float*)d_in[8]};
    const float* W_out = (const float*)d_in[9];
    const float* b_out = (const float*)d_in[10];
    float* out = (float*)d_out;

    cudaFuncSetAttribute(gemm_tc, cudaFuncAttributeMaxDynamicSharedMemorySize, SMEM_GEMM);

    float *b0, *b1, *b2, *b3, *s1;
    cudaGetSymbolAddress((void**)&b0, g_b0);
    cudaGetSymbolAddress((void**)&b1, g_b1);
    cudaGetSymbolAddress((void**)&b2, g_b2);
    cudaGetSymbolAddress((void**)&b3, g_b3);
    cudaGetSymbolAddress((void**)&s1, g_s1);
    unsigned short *xh, *xl, *winh, *winl, *hah, *hal, *hbh, *hbl;
    unsigned short *wh, *wl, *s0h, *s0l, *mih, *mil, *woh, *wol;
    cudaGetSymbolAddress((void**)&xh, g_xh);   cudaGetSymbolAddress((void**)&xl, g_xl);
    cudaGetSymbolAddress((void**)&winh, g_winh); cudaGetSymbolAddress((void**)&winl, g_winl);
    cudaGetSymbolAddress((void**)&hah, g_hah); cudaGetSymbolAddress((void**)&hal, g_hal);
    cudaGetSymbolAddress((void**)&hbh, g_hbh); cudaGetSymbolAddress((void**)&hbl, g_hbl);
    cudaGetSymbolAddress((void**)&wh, g_wh);   cudaGetSymbolAddress((void**)&wl, g_wl);
    cudaGetSymbolAddress((void**)&s0h, g_s0h); cudaGetSymbolAddress((void**)&s0l, g_s0l);
    cudaGetSymbolAddress((void**)&mih, g_mih); cudaGetSymbolAddress((void**)&mil, g_mil);
    cudaGetSymbolAddress((void**)&woh, g_woh); cudaGetSymbolAddress((void**)&wol, g_wol);

    const int NB = BATCH * UNITS;
    dim3 gBig(UNITS / BN, BATCH / BM);                 // (16, 64)
    dim3 gSmall(UNITS / BN, UNITS / BM);               // (16, 8)
    dim3 gOut((OUTDIM + BN - 1) / BN, BATCH / BM);     // (16, 64)
    dim3 tblk(32, 32), tgrid(UNITS / 32, UNITS / 32);
    int ewBlocks = (NB + 255) / 256;
    int sdBlocks = (UNITS * UNITS + 255) / 256;

    // one-time splits of inputs
    split_hl<<<(BATCH * INDIM / 4 + 255) / 256, 256>>>(x, xh, xl, BATCH * INDIM);
    split_hl<<<(UNITS * INDIM / 4 + 255) / 256, 256>>>(W_in, winh, winl, UNITS * INDIM);
    split_hl<<<(OUTDIM * UNITS / 4 + 255) / 256, 256>>>(W_out, woh, wol, OUTDIM * UNITS);

    // z0 = x @ W_in^T + b_in -> b0 (u_in), relu(z0) -> b1 (v_in), fused
    gemm_tc<<<gBig, 256, SMEM_GEMM>>>(xh, xl, winh, winl, b0, b1, nullptr, nullptr,
                                      BATCH, UNITS, INDIM, 1.0f, b_in, 0.0f,
                                      nullptr, 0.0f);

    float* pu  = b0;
    float* pv  = b1;
    float* pru = b2;
    float* prv = b3;

    for (int l = 0; l < 3; ++l) {
        const float* W  = Ws[l];
        const float* bb = bs[l];
        float sv = (l == 0) ? 1.0f : -1.0f;

        // W -> (wh, wl) and W^T -> (s0h, s0l), one read of W
        weight_split_both<<<tgrid, tblk>>>(wh, wl, s0h, s0l, W, UNITS);
        // K = W^T W   (fp32 only)
        gemm_tc<<<gSmall, 256, SMEM_GEMM>>>(s0h, s0l, s0h, s0l, s1, nullptr,
                                            nullptr, nullptr,
                                            UNITS, UNITS, UNITS, 1.0f, nullptr, 0.0f,
                                            nullptr, 0.0f);
        // Minv = (1/c)(I - aK)  [first-order Neumann], emitted as hi/lo
        scale_diag_split<<<sdBlocks, 256>>>(mih, mil, s1, -ACONST / CCONST,
                                            1.0f / CCONST, UNITS);

        build_rhs_split<<<ewBlocks, 256>>>(pu, pv, bb, sv, pru, hah, hal, prv, NB);
        // r = dt*Ru@W + Rv  (B = W^T); only splits needed downstream
        gemm_tc<<<gBig, 256, SMEM_GEMM>>>(hah, hal, s0h, s0l, nullptr, nullptr,
                                          hbh, hbl,
                                          BATCH, UNITS, UNITS, DT, nullptr, 0.0f,
                                          prv, 1.0f);
        // V = r @ Minv  (Minv symmetric -> NT ok)
        gemm_tc<<<gBig, 256, SMEM_GEMM>>>(hbh, hbl, mih, mil, prv, nullptr,
                                          hah, hal,
                                          BATCH, UNITS, UNITS, 1.0f, nullptr, 0.0f,
                                          nullptr, 0.0f);
        // u_out = dt*V@W^T - Ru ; splits only needed after the last layer
        gemm_tc<<<gBig, 256, SMEM_GEMM>>>(hah, hal, wh, wl, pu, nullptr,
                                          (l == 2) ? hbh : nullptr,
                                          (l == 2) ? hbl : nullptr,
                                          BATCH, UNITS, UNITS, DT, nullptr, 0.0f,
                                          pru, -1.0f);

        float* tmp = pv; pv = prv; prv = tmp;
    }

    // logits = u @ W_out^T + b_out -> out ; softmax
    gemm_tc<<<gOut, 256, SMEM_GEMM>>>(hbh, hbl, woh, wol, out, nullptr,
                                      nullptr, nullptr,
                                      BATCH, OUTDIM, UNITS, 1.0f, b_out, 0.0f,
                                      nullptr, 0.0f);
    softmax_rows<<<BATCH, 256>>>(out, OUTDIM);
}